// round 2
// baseline (speedup 1.0000x reference)
#include <cuda_runtime.h>
#include <math.h>
#include <stdint.h>

// Problem constants
#define NNODE 20000
#define NEDGE 320000
#define INDIM 256
#define NB 64
#define H0 4
#define C0 128
#define D0 512   // H0*C0
#define H1 4
#define C1 64
#define D1 256   // H1*C1
#define NEG_SLOPE 0.2f
#define BN_EPS 1e-5f

// ---------------- scratch layout (floats) ----------------
#define OFF_XL0  ((size_t)0)
#define OFF_XR0  ((size_t)10240000)
#define OFF_H0   ((size_t)20480000)
#define OFF_XL1  ((size_t)30720000)
#define OFF_XR1  ((size_t)35840000)
#define OFF_AGG1 ((size_t)40960000)
#define OFF_H1   ((size_t)46080000)
#define OFF_E    ((size_t)47360000)
#define OFF_SMAX ((size_t)48640000)
#define OFF_SSUM ((size_t)48720000)
#define OFF_BNS  ((size_t)48800000)
#define OFF_POOL ((size_t)48801024)
#define OFF_CNT  ((size_t)48805120)
#define OFF_Z1   ((size_t)48805184)
#define OFF_Z2   ((size_t)48821568)
#define SCRATCH_FLOATS ((size_t)48829760)

__device__ __align__(256) float g_scratch[SCRATCH_FLOATS];

// ---------------- helpers ----------------
__device__ __forceinline__ float atomicMaxFloat(float* addr, float value) {
    float old;
    if (value >= 0.0f)
        old = __int_as_float(atomicMax((int*)addr, __float_as_int(value)));
    else
        old = __uint_as_float(atomicMin((unsigned int*)addr, __float_as_uint(value)));
    return old;
}

__global__ void fill_kernel(float* p, float v, size_t n) {
    size_t i = (size_t)blockIdx.x * blockDim.x + threadIdx.x;
    size_t stride = (size_t)gridDim.x * blockDim.x;
    for (; i < n; i += stride) p[i] = v;
}

// ---------------- SGEMM: C[M,N] = A[M,K] @ B[K,N] ----------------
// BM=BN=128, BK=8, 256 threads, 8x8 microtile. N % 128 == 0, K % 8 == 0 assumed.
__global__ __launch_bounds__(256) void sgemm128(
    const float* __restrict__ A, const float* __restrict__ B, float* __restrict__ C,
    int M, int N, int K)
{
    __shared__ float As[8][128];
    __shared__ float Bs[8][128];
    const int tid = threadIdx.x;
    const int bx = blockIdx.x;   // along N
    const int by = blockIdx.y;   // along M
    const int trow = tid / 16;   // 0..15
    const int tcol = tid % 16;   // 0..15

    const int arow = tid >> 1;          // 0..127
    const int acol = (tid & 1) * 4;     // 0 or 4
    const int brow = tid >> 5;          // 0..7
    const int bcol = (tid & 31) * 4;    // 0..124

    float acc[8][8];
#pragma unroll
    for (int i = 0; i < 8; i++)
#pragma unroll
        for (int j = 0; j < 8; j++) acc[i][j] = 0.0f;

    for (int k0 = 0; k0 < K; k0 += 8) {
        int gr = by * 128 + arow;
        float4 av;
        if (gr < M) av = *(const float4*)(A + (size_t)gr * K + k0 + acol);
        else av = make_float4(0.f, 0.f, 0.f, 0.f);
        As[acol + 0][arow] = av.x;
        As[acol + 1][arow] = av.y;
        As[acol + 2][arow] = av.z;
        As[acol + 3][arow] = av.w;

        float4 bv = *(const float4*)(B + (size_t)(k0 + brow) * N + bx * 128 + bcol);
        *(float4*)&Bs[brow][bcol] = bv;
        __syncthreads();

#pragma unroll
        for (int kk = 0; kk < 8; kk++) {
            float a[8], b[8];
#pragma unroll
            for (int i = 0; i < 8; i++) a[i] = As[kk][trow * 8 + i];
#pragma unroll
            for (int j = 0; j < 8; j++) b[j] = Bs[kk][tcol * 8 + j];
#pragma unroll
            for (int i = 0; i < 8; i++)
#pragma unroll
                for (int j = 0; j < 8; j++) acc[i][j] = fmaf(a[i], b[j], acc[i][j]);
        }
        __syncthreads();
    }

#pragma unroll
    for (int i = 0; i < 8; i++) {
        int r = by * 128 + trow * 8 + i;
        if (r < M) {
            int cbase = bx * 128 + tcol * 8;
            float4 v0 = make_float4(acc[i][0], acc[i][1], acc[i][2], acc[i][3]);
            float4 v1 = make_float4(acc[i][4], acc[i][5], acc[i][6], acc[i][7]);
            *(float4*)(C + (size_t)r * N + cbase)     = v0;
            *(float4*)(C + (size_t)r * N + cbase + 4) = v1;
        }
    }
}

// ---------------- GATv2 edge score: warp per (edge, head) ----------------
template <int C>
__global__ void edge_score_kernel(
    const float* __restrict__ xl, const float* __restrict__ xr,
    const int* __restrict__ ei, const float* __restrict__ ea,
    const float* __restrict__ we, const float* __restrict__ att,
    float* __restrict__ e_out, float* __restrict__ segmax)
{
    const int H = 4;
    int wg = (int)(((size_t)blockIdx.x * blockDim.x + threadIdx.x) >> 5);
    int lane = threadIdx.x & 31;
    if (wg >= NEDGE * H) return;
    int edge = wg >> 2;
    int h = wg & 3;
    int src = ei[edge];
    int dst = ei[NEDGE + edge];
    float eav = ea[edge];
    const float* xls = xl + (size_t)src * (H * C) + h * C;
    const float* xrd = xr + (size_t)dst * (H * C) + h * C;
    const float* wh = we + h * C;
    const float* ah = att + h * C;
    float s = 0.0f;
#pragma unroll
    for (int c = lane; c < C; c += 32) {
        float m = xls[c] + xrd[c] + eav * wh[c];
        m = m > 0.0f ? m : NEG_SLOPE * m;
        s += m * ah[c];
    }
#pragma unroll
    for (int o = 16; o; o >>= 1) s += __shfl_xor_sync(0xffffffff, s, o);
    if (lane == 0) {
        e_out[edge * H + h] = s;
        atomicMaxFloat(&segmax[dst * H + h], s);
    }
}

// ---------------- exp + segment sum ----------------
__global__ void edge_exp_kernel(
    float* __restrict__ e, const int* __restrict__ ei,
    const float* __restrict__ segmax, float* __restrict__ segsum)
{
    int idx = blockIdx.x * blockDim.x + threadIdx.x;
    if (idx >= NEDGE * 4) return;
    int edge = idx >> 2;
    int h = idx & 3;
    int dst = ei[NEDGE + edge];
    float v = expf(e[idx] - segmax[dst * 4 + h]);
    e[idx] = v;
    atomicAdd(&segsum[dst * 4 + h], v);
}

// ---------------- weighted aggregation: warp per (edge, head) ----------------
template <int C>
__global__ void aggregate_kernel(
    const float* __restrict__ xl, const float* __restrict__ e,
    const int* __restrict__ ei, const float* __restrict__ segsum,
    float* __restrict__ out)
{
    const int H = 4;
    int wg = (int)(((size_t)blockIdx.x * blockDim.x + threadIdx.x) >> 5);
    int lane = threadIdx.x & 31;
    if (wg >= NEDGE * H) return;
    int edge = wg >> 2;
    int h = wg & 3;
    int src = ei[edge];
    int dst = ei[NEDGE + edge];
    float alpha = e[edge * H + h] / (segsum[dst * H + h] + 1e-16f);
    const float* xls = xl + (size_t)src * (H * C) + h * C;
    float* od = out + (size_t)dst * (H * C) + h * C;
#pragma unroll
    for (int c = lane; c < C; c += 32)
        atomicAdd(&od[c], alpha * xls[c]);
}

// ---------------- BN statistics (two pass): block = C threads, 64 rows per block --------
__global__ void bn_stats_kernel(
    const float* __restrict__ h, const float* __restrict__ bias,
    int n, int C, float* __restrict__ sums)
{
    int c = threadIdx.x;
    float b = bias ? bias[c] : 0.0f;
    int r0 = blockIdx.x * 64;
    int r1 = min(r0 + 64, n);
    float s = 0.0f, s2 = 0.0f;
    for (int r = r0; r < r1; r++) {
        float v = h[(size_t)r * C + c] + b;
        s += v;
        s2 += v * v;
    }
    atomicAdd(&sums[c], s);
    atomicAdd(&sums[C + c], s2);
}

__global__ void bn_apply_elu_kernel(
    float* __restrict__ h, const float* __restrict__ bias,
    const float* __restrict__ sums, const float* __restrict__ g,
    const float* __restrict__ b, int n, int C)
{
    size_t total = (size_t)n * C;
    size_t i = (size_t)blockIdx.x * blockDim.x + threadIdx.x;
    size_t stride = (size_t)gridDim.x * blockDim.x;
    float inv_n = 1.0f / n;
    for (; i < total; i += stride) {
        int c = (int)(i % C);
        float mu = sums[c] * inv_n;
        float var = sums[C + c] * inv_n - mu * mu;
        float v = h[i] + (bias ? bias[c] : 0.0f);
        v = (v - mu) * rsqrtf(var + BN_EPS) * g[c] + b[c];
        h[i] = v > 0.0f ? v : expm1f(v);
    }
}

// ---------------- mean over heads (layer 1) ----------------
__global__ void head_mean_kernel(const float* __restrict__ agg, float* __restrict__ h1)
{
    int idx = blockIdx.x * blockDim.x + threadIdx.x;
    if (idx >= NNODE * C1) return;
    int node = idx >> 6;
    int c = idx & 63;
    const float* a = agg + (size_t)node * D1;
    h1[idx] = 0.25f * (a[c] + a[64 + c] + a[128 + c] + a[192 + c]);
}

// ---------------- global mean pool ----------------
__global__ void pool_kernel(
    const float* __restrict__ h1, const int* __restrict__ batch,
    float* __restrict__ pool, float* __restrict__ cnt)
{
    int idx = blockIdx.x * blockDim.x + threadIdx.x;
    if (idx >= NNODE * 64) return;
    int node = idx >> 6;
    int c = idx & 63;
    int b = batch[node];
    atomicAdd(&pool[b * 64 + c], h1[idx]);
    if (c == 0) atomicAdd(&cnt[b], 1.0f);
}

// ---------------- classifier: one block, 256 threads ----------------
__global__ __launch_bounds__(256) void classifier_kernel(
    const float* __restrict__ pool, const float* __restrict__ cnt,
    const float* __restrict__ w1, const float* __restrict__ b1,
    const float* __restrict__ bn1g, const float* __restrict__ bn1b,
    const float* __restrict__ w2, const float* __restrict__ b2,
    const float* __restrict__ bn2g, const float* __restrict__ bn2b,
    const float* __restrict__ w3, const float* __restrict__ b3,
    float* __restrict__ z1, float* __restrict__ z2,
    float* __restrict__ out, int out_size)
{
    __shared__ float emb[64 * 64];
    __shared__ float sc1[256], sh1[256];
    __shared__ float sc2[128], sh2[128];
    int tid = threadIdx.x;

    // emb = pool / max(cnt,1)
    for (int i = tid; i < 64 * 64; i += 256) {
        int b = i >> 6;
        emb[i] = pool[i] / fmaxf(cnt[b], 1.0f);
    }
    __syncthreads();

    // write emb to output (tuple order: logits then emb)
    if (out_size >= 4224) {
        for (int i = tid; i < 4096; i += 256) out[128 + i] = emb[i];
    }

    // z1 = emb @ w1 + b1   [64,256]
    for (int i = tid; i < 64 * 256; i += 256) {
        int b = i >> 8, j = i & 255;
        float s = b1[j];
        const float* er = emb + b * 64;
        for (int k = 0; k < 64; k++) s = fmaf(er[k], w1[k * 256 + j], s);
        z1[i] = s;
    }
    __syncthreads();

    // BN over 64 rows, 256 channels
    if (tid < 256) {
        float s = 0.f, s2 = 0.f;
        for (int b = 0; b < 64; b++) {
            float v = z1[b * 256 + tid];
            s += v; s2 += v * v;
        }
        float mu = s / 64.f;
        float var = s2 / 64.f - mu * mu;
        float sc = rsqrtf(var + BN_EPS) * bn1g[tid];
        sc1[tid] = sc;
        sh1[tid] = bn1b[tid] - mu * sc;
    }
    __syncthreads();
    for (int i = tid; i < 64 * 256; i += 256) {
        float v = z1[i] * sc1[i & 255] + sh1[i & 255];
        z1[i] = v > 0.f ? v : expm1f(v);
    }
    __syncthreads();

    // z2 = z1 @ w2 + b2   [64,128]
    for (int i = tid; i < 64 * 128; i += 256) {
        int b = i >> 7, j = i & 127;
        float s = b2[j];
        const float* zr = z1 + b * 256;
        for (int k = 0; k < 256; k++) s = fmaf(zr[k], w2[k * 128 + j], s);
        z2[i] = s;
    }
    __syncthreads();

    // BN over 64 rows, 128 channels
    if (tid < 128) {
        float s = 0.f, s2 = 0.f;
        for (int b = 0; b < 64; b++) {
            float v = z2[b * 128 + tid];
            s += v; s2 += v * v;
        }
        float mu = s / 64.f;
        float var = s2 / 64.f - mu * mu;
        float sc = rsqrtf(var + BN_EPS) * bn2g[tid];
        sc2[tid] = sc;
        sh2[tid] = bn2b[tid] - mu * sc;
    }
    __syncthreads();
    for (int i = tid; i < 64 * 128; i += 256) {
        float v = z2[i] * sc2[i & 127] + sh2[i & 127];
        z2[i] = v > 0.f ? v : expm1f(v);
    }
    __syncthreads();

    // logits = z2 @ w3 + b3   [64,2]
    if (tid < 128) {
        int b = tid >> 1, j = tid & 1;
        float s = b3[j];
        const float* zr = z2 + b * 128;
        for (int k = 0; k < 128; k++) s = fmaf(zr[k], w3[k * 2 + j], s);
        if (out_size >= 128) out[b * 2 + j] = s;
    }
}

// ---------------- launch ----------------
extern "C" void kernel_launch(void* const* d_in, const int* in_sizes, int n_in,
                              void* d_out, int out_size)
{
    const float* x       = (const float*)d_in[0];
    const int*   ei      = (const int*)d_in[1];
    const float* ea      = (const float*)d_in[2];
    const int*   bat     = (const int*)d_in[3];
    const float* g0_wl   = (const float*)d_in[4];
    const float* g0_wr   = (const float*)d_in[5];
    const float* g0_we   = (const float*)d_in[6];
    const float* g0_att  = (const float*)d_in[7];
    const float* g0_bias = (const float*)d_in[8];
    const float* bn0_g   = (const float*)d_in[9];
    const float* bn0_b   = (const float*)d_in[10];
    const float* g1_wl   = (const float*)d_in[11];
    const float* g1_wr   = (const float*)d_in[12];
    const float* g1_we   = (const float*)d_in[13];
    const float* g1_att  = (const float*)d_in[14];
    const float* g1_bias = (const float*)d_in[15];
    const float* bn1_g   = (const float*)d_in[16];
    const float* bn1_b   = (const float*)d_in[17];
    const float* c_w1    = (const float*)d_in[18];
    const float* c_b1    = (const float*)d_in[19];
    const float* cbn1_g  = (const float*)d_in[20];
    const float* cbn1_b  = (const float*)d_in[21];
    const float* c_w2    = (const float*)d_in[22];
    const float* c_b2    = (const float*)d_in[23];
    const float* cbn2_g  = (const float*)d_in[24];
    const float* cbn2_b  = (const float*)d_in[25];
    const float* c_w3    = (const float*)d_in[26];
    const float* c_b3    = (const float*)d_in[27];
    float* out = (float*)d_out;

    float* S = nullptr;
    cudaGetSymbolAddress((void**)&S, g_scratch);
    float* xl0  = S + OFF_XL0;
    float* xr0  = S + OFF_XR0;
    float* h0   = S + OFF_H0;
    float* xl1  = S + OFF_XL1;
    float* xr1  = S + OFF_XR1;
    float* agg1 = S + OFF_AGG1;
    float* h1   = S + OFF_H1;
    float* e    = S + OFF_E;
    float* smax = S + OFF_SMAX;
    float* ssum = S + OFF_SSUM;
    float* bns  = S + OFF_BNS;
    float* pool = S + OFF_POOL;
    float* cnt  = S + OFF_CNT;
    float* z1   = S + OFF_Z1;
    float* z2   = S + OFF_Z2;

    const int warpBlocks = (NEDGE * 4 * 32) / 256;          // 160000
    const int ehBlocks   = (NEDGE * 4 + 255) / 256;

    // ---- layer 0 init ----
    fill_kernel<<<4096, 256>>>(h0, 0.0f, (size_t)NNODE * D0);
    fill_kernel<<<256, 256>>>(ssum, 0.0f, (size_t)NNODE * 4);
    fill_kernel<<<256, 256>>>(smax, -INFINITY, (size_t)NNODE * 4);
    fill_kernel<<<4, 256>>>(bns, 0.0f, 1024);
    fill_kernel<<<17, 256>>>(pool, 0.0f, 64 * 64 + 64);     // pool + cnt contiguous

    // ---- layer 0 ----
    dim3 g0grid(D0 / 128, (NNODE + 127) / 128);
    sgemm128<<<g0grid, 256>>>(x, g0_wl, xl0, NNODE, D0, INDIM);
    sgemm128<<<g0grid, 256>>>(x, g0_wr, xr0, NNODE, D0, INDIM);
    edge_score_kernel<C0><<<warpBlocks, 256>>>(xl0, xr0, ei, ea, g0_we, g0_att, e, smax);
    edge_exp_kernel<<<ehBlocks, 256>>>(e, ei, smax, ssum);
    aggregate_kernel<C0><<<warpBlocks, 256>>>(xl0, e, ei, ssum, h0);
    bn_stats_kernel<<<(NNODE + 63) / 64, D0>>>(h0, g0_bias, NNODE, D0, bns);
    bn_apply_elu_kernel<<<2048, 256>>>(h0, g0_bias, bns, bn0_g, bn0_b, NNODE, D0);

    // ---- layer 1 init ----
    fill_kernel<<<2048, 256>>>(agg1, 0.0f, (size_t)NNODE * D1);
    fill_kernel<<<256, 256>>>(ssum, 0.0f, (size_t)NNODE * 4);
    fill_kernel<<<256, 256>>>(smax, -INFINITY, (size_t)NNODE * 4);
    fill_kernel<<<4, 256>>>(bns, 0.0f, 1024);

    // ---- layer 1 ----
    dim3 g1grid(D1 / 128, (NNODE + 127) / 128);
    sgemm128<<<g1grid, 256>>>(h0, g1_wl, xl1, NNODE, D1, D0);
    sgemm128<<<g1grid, 256>>>(h0, g1_wr, xr1, NNODE, D1, D0);
    edge_score_kernel<C1><<<warpBlocks, 256>>>(xl1, xr1, ei, ea, g1_we, g1_att, e, smax);
    edge_exp_kernel<<<ehBlocks, 256>>>(e, ei, smax, ssum);
    aggregate_kernel<C1><<<warpBlocks, 256>>>(xl1, e, ei, ssum, agg1);
    head_mean_kernel<<<(NNODE * C1 + 255) / 256, 256>>>(agg1, h1);
    bn_stats_kernel<<<(NNODE + 63) / 64, C1>>>(h1, g1_bias, NNODE, C1, bns);
    bn_apply_elu_kernel<<<1024, 256>>>(h1, g1_bias, bns, bn1_g, bn1_b, NNODE, C1);

    // ---- pool + classifier ----
    pool_kernel<<<(NNODE * 64 + 255) / 256, 256>>>(h1, bat, pool, cnt);
    classifier_kernel<<<1, 256>>>(pool, cnt,
                                  c_w1, c_b1, cbn1_g, cbn1_b,
                                  c_w2, c_b2, cbn2_g, cbn2_b,
                                  c_w3, c_b3, z1, z2, out, out_size);
}

// round 4
// speedup vs baseline: 1.3677x; 1.3677x over previous
#include <cuda_runtime.h>
#include <cuda_bf16.h>
#include <math.h>
#include <stdint.h>

// Problem constants
#define NNODE 20000
#define NEDGE 320000
#define INDIM 256
#define NB 64
#define H0 4
#define C0 128
#define D0 512   // H0*C0
#define H1 4
#define C1 64
#define D1 256   // H1*C1
#define NEG_SLOPE 0.2f
#define BN_EPS 1e-5f

#define MPAD 20096   // 157 * 128
#define NMT 157

// ---------------- fp32 scratch layout (floats) ----------------
#define OFF_XL0  ((size_t)0)
#define OFF_XR0  ((size_t)10240000)
#define OFF_H0   ((size_t)20480000)
#define OFF_XL1  ((size_t)30720000)
#define OFF_XR1  ((size_t)35840000)
#define OFF_AGG1 ((size_t)40960000)
#define OFF_H1   ((size_t)46080000)
#define OFF_E    ((size_t)47360000)
#define OFF_SMAX ((size_t)48640000)
#define OFF_SSUM ((size_t)48720000)
#define OFF_BNS  ((size_t)48800000)
#define OFF_POOL ((size_t)48801024)
#define OFF_CNT  ((size_t)48805120)
#define OFF_Z1   ((size_t)48805184)
#define OFF_Z2   ((size_t)48821568)
#define SCRATCH_FLOATS ((size_t)48829760)

__device__ __align__(256) float g_scratch[SCRATCH_FLOATS];

// ---------------- bf16 operand scratch (hi/lo pairs) ----------------
#define BF_A0  ((size_t)0)          // hi: MPAD*256, lo: MPAD*256  = 10289152
#define BF_A1  ((size_t)10289152)   // hi: MPAD*512, lo: MPAD*512  = 20578304
#define BF_B0L ((size_t)30867456)   // Bt 512x256 hi+lo = 262144
#define BF_B0R ((size_t)31129600)
#define BF_B1L ((size_t)31391744)   // Bt 256x512 hi+lo = 262144
#define BF_B1R ((size_t)31653888)
#define BF_TOTAL ((size_t)31916032)

__device__ __align__(1024) __nv_bfloat16 g_bf[BF_TOTAL];

// ================= PTX helpers (portable sm_80+ only) =================
__device__ __forceinline__ uint32_t smem_to_u32(const void* p) {
    uint32_t a;
    asm("{ .reg .u64 t; cvta.to.shared.u64 t, %1; cvt.u32.u64 %0, t; }" : "=r"(a) : "l"(p));
    return a;
}
__device__ __forceinline__ void ldsm_x4(uint32_t* r, uint32_t addr) {
    asm volatile("ldmatrix.sync.aligned.m8n8.x4.shared.b16 {%0,%1,%2,%3}, [%4];"
        : "=r"(r[0]), "=r"(r[1]), "=r"(r[2]), "=r"(r[3]) : "r"(addr));
}
__device__ __forceinline__ void ldsm_x2(uint32_t* r, uint32_t addr) {
    asm volatile("ldmatrix.sync.aligned.m8n8.x2.shared.b16 {%0,%1}, [%2];"
        : "=r"(r[0]), "=r"(r[1]) : "r"(addr));
}
__device__ __forceinline__ void mma_bf16(float* d, const uint32_t* a, const uint32_t* b) {
    asm volatile(
        "mma.sync.aligned.m16n8k16.row.col.f32.bf16.bf16.f32 "
        "{%0,%1,%2,%3}, {%4,%5,%6,%7}, {%8,%9}, {%0,%1,%2,%3};"
        : "+f"(d[0]), "+f"(d[1]), "+f"(d[2]), "+f"(d[3])
        : "r"(a[0]), "r"(a[1]), "r"(a[2]), "r"(a[3]), "r"(b[0]), "r"(b[1]));
}

// ================= operand conversion =================
// A [Mreal x K] fp32 -> hi/lo bf16 [Mpad x K] row-major, rows >= Mreal zeroed
__global__ void convA_kernel(const float* __restrict__ A, __nv_bfloat16* __restrict__ hi,
                             __nv_bfloat16* __restrict__ lo, int Mreal, int Mpad, int K) {
    size_t i4 = (size_t)blockIdx.x * blockDim.x + threadIdx.x;
    size_t total = (size_t)Mpad * K / 4;
    if (i4 >= total) return;
    size_t base = i4 * 4;
    int row = (int)(base / K);
    float4 v = make_float4(0.f, 0.f, 0.f, 0.f);
    if (row < Mreal) v = *(const float4*)(A + base);
    float a[4] = {v.x, v.y, v.z, v.w};
    __nv_bfloat16 h[4], l[4];
#pragma unroll
    for (int j = 0; j < 4; j++) {
        h[j] = __float2bfloat16(a[j]);
        l[j] = __float2bfloat16(a[j] - __bfloat162float(h[j]));
    }
    __nv_bfloat162* hp = (__nv_bfloat162*)(hi + base);
    __nv_bfloat162* lp = (__nv_bfloat162*)(lo + base);
    __nv_bfloat162 t;
    t.x = h[0]; t.y = h[1]; hp[0] = t;
    t.x = h[2]; t.y = h[3]; hp[1] = t;
    t.x = l[0]; t.y = l[1]; lp[0] = t;
    t.x = l[2]; t.y = l[3]; lp[1] = t;
}

// W [K x N] fp32 -> Bt hi/lo [N x K] row-major (transposed)
__global__ void convB_kernel(const float* __restrict__ W, __nv_bfloat16* __restrict__ hi,
                             __nv_bfloat16* __restrict__ lo, int K, int N) {
    int idx = blockIdx.x * blockDim.x + threadIdx.x;
    if (idx >= N * K) return;
    int n = idx / K, k = idx % K;
    float a = W[(size_t)k * N + n];
    __nv_bfloat16 h = __float2bfloat16(a);
    hi[idx] = h;
    lo[idx] = __float2bfloat16(a - __bfloat162float(h));
}

// ================= bf16x3 mma.sync GEMM =================
// C[M x N] = A @ W  where Bt = W^T [N x K].
// Block 128x128, BK=64, 8 warps (2x4), warp tile 64x32.
#define LDA 72   // padded smem stride (bf16 elems), 144B
__global__ __launch_bounds__(256) void mma_gemm_kernel(
    const __nv_bfloat16* __restrict__ Ah, const __nv_bfloat16* __restrict__ Al,
    const __nv_bfloat16* __restrict__ Bh, const __nv_bfloat16* __restrict__ Bl,
    float* __restrict__ C, int Mreal, int N, int K)
{
    extern __shared__ __align__(16) char smem[];
    __nv_bfloat16* sAh = (__nv_bfloat16*)smem;       // 128*LDA
    __nv_bfloat16* sAl = sAh + 128 * LDA;
    __nv_bfloat16* sBh = sAl + 128 * LDA;
    __nv_bfloat16* sBl = sBh + 128 * LDA;
    uint32_t sbase = smem_to_u32(smem);
    const uint32_t oAh = 0;
    const uint32_t oAl = 128 * LDA * 2;
    const uint32_t oBh = 2 * 128 * LDA * 2;
    const uint32_t oBl = 3 * 128 * LDA * 2;

    int tid = threadIdx.x, wid = tid >> 5, lane = tid & 31;
    int mt = blockIdx.y, nt = blockIdx.x;
    int wm = wid >> 2;   // 0..1
    int wn = wid & 3;    // 0..3

    float acc[4][4][4];
#pragma unroll
    for (int i = 0; i < 4; i++)
#pragma unroll
        for (int j = 0; j < 4; j++)
#pragma unroll
            for (int q = 0; q < 4; q++) acc[i][j][q] = 0.f;

    const int chunk = tid & 7;      // 8 x uint4 per 64-elem row
    const int row4  = tid >> 3;     // 32 rows per pass

    for (int k0 = 0; k0 < K; k0 += 64) {
#pragma unroll
        for (int p = 0; p < 4; p++) {
            int r = row4 + p * 32;
            size_t ga = (size_t)(mt * 128 + r) * K + k0 + chunk * 8;
            size_t gb = (size_t)(nt * 128 + r) * K + k0 + chunk * 8;
            *(uint4*)(sAh + r * LDA + chunk * 8) = *(const uint4*)(Ah + ga);
            *(uint4*)(sAl + r * LDA + chunk * 8) = *(const uint4*)(Al + ga);
            *(uint4*)(sBh + r * LDA + chunk * 8) = *(const uint4*)(Bh + gb);
            *(uint4*)(sBl + r * LDA + chunk * 8) = *(const uint4*)(Bl + gb);
        }
        __syncthreads();

#pragma unroll
        for (int ks = 0; ks < 4; ks++) {
            uint32_t ah[4][4], al[4][4], bh[4][2], bl[4][2];
            // A frag addresses: row = wm*64 + i*16 + (lane&15), col = ks*16 + (lane>>4)*8
            uint32_t arow = (uint32_t)(wm * 64 + (lane & 15));
            uint32_t acol = (uint32_t)(ks * 16 + (lane >> 4) * 8);
#pragma unroll
            for (int i = 0; i < 4; i++) {
                uint32_t off = ((arow + i * 16) * LDA + acol) * 2;
                ldsm_x4(ah[i], sbase + oAh + off);
                ldsm_x4(al[i], sbase + oAl + off);
            }
            // B frag: n-row = wn*32 + j*8 + (lane&7), col = ks*16 + ((lane>>3)&1)*8
            uint32_t brow = (uint32_t)(wn * 32 + (lane & 7));
            uint32_t bcol = (uint32_t)(ks * 16 + ((lane >> 3) & 1) * 8);
#pragma unroll
            for (int j = 0; j < 4; j++) {
                uint32_t off = ((brow + j * 8) * LDA + bcol) * 2;
                ldsm_x2(bh[j], sbase + oBh + off);
                ldsm_x2(bl[j], sbase + oBl + off);
            }
#pragma unroll
            for (int i = 0; i < 4; i++)
#pragma unroll
                for (int j = 0; j < 4; j++) {
                    mma_bf16(acc[i][j], ah[i], bh[j]);
                    mma_bf16(acc[i][j], ah[i], bl[j]);
                    mma_bf16(acc[i][j], al[i], bh[j]);
                }
        }
        __syncthreads();
    }

    // epilogue
#pragma unroll
    for (int i = 0; i < 4; i++) {
        int r0 = mt * 128 + wm * 64 + i * 16 + (lane >> 2);
        int r1 = r0 + 8;
#pragma unroll
        for (int j = 0; j < 4; j++) {
            int c = nt * 128 + wn * 32 + j * 8 + (lane & 3) * 2;
            if (r0 < Mreal)
                *(float2*)(C + (size_t)r0 * N + c) = make_float2(acc[i][j][0], acc[i][j][1]);
            if (r1 < Mreal)
                *(float2*)(C + (size_t)r1 * N + c) = make_float2(acc[i][j][2], acc[i][j][3]);
        }
    }
}
#define GEMM_SMEM (4 * 128 * LDA * 2)

// ================= misc helpers =================
__device__ __forceinline__ float atomicMaxFloat(float* addr, float value) {
    float old;
    if (value >= 0.0f)
        old = __int_as_float(atomicMax((int*)addr, __float_as_int(value)));
    else
        old = __uint_as_float(atomicMin((unsigned int*)addr, __float_as_uint(value)));
    return old;
}

__global__ void fill_kernel(float* p, float v, size_t n) {
    size_t i = (size_t)blockIdx.x * blockDim.x + threadIdx.x;
    size_t stride = (size_t)gridDim.x * blockDim.x;
    for (; i < n; i += stride) p[i] = v;
}

// ---------------- GATv2 edge score: warp per (edge, head) ----------------
template <int C>
__global__ void edge_score_kernel(
    const float* __restrict__ xl, const float* __restrict__ xr,
    const int* __restrict__ ei, const float* __restrict__ ea,
    const float* __restrict__ we, const float* __restrict__ att,
    float* __restrict__ e_out, float* __restrict__ segmax)
{
    const int H = 4;
    int wg = (int)(((size_t)blockIdx.x * blockDim.x + threadIdx.x) >> 5);
    int lane = threadIdx.x & 31;
    if (wg >= NEDGE * H) return;
    int edge = wg >> 2;
    int h = wg & 3;
    int src = ei[edge];
    int dst = ei[NEDGE + edge];
    float eav = ea[edge];
    const float* xls = xl + (size_t)src * (H * C) + h * C;
    const float* xrd = xr + (size_t)dst * (H * C) + h * C;
    const float* wh = we + h * C;
    const float* ah = att + h * C;
    float s = 0.0f;
#pragma unroll
    for (int c = lane; c < C; c += 32) {
        float m = xls[c] + xrd[c] + eav * wh[c];
        m = m > 0.0f ? m : NEG_SLOPE * m;
        s += m * ah[c];
    }
#pragma unroll
    for (int o = 16; o; o >>= 1) s += __shfl_xor_sync(0xffffffff, s, o);
    if (lane == 0) {
        e_out[edge * H + h] = s;
        atomicMaxFloat(&segmax[dst * H + h], s);
    }
}

__global__ void edge_exp_kernel(
    float* __restrict__ e, const int* __restrict__ ei,
    const float* __restrict__ segmax, float* __restrict__ segsum)
{
    int idx = blockIdx.x * blockDim.x + threadIdx.x;
    if (idx >= NEDGE * 4) return;
    int edge = idx >> 2;
    int h = idx & 3;
    int dst = ei[NEDGE + edge];
    float v = expf(e[idx] - segmax[dst * 4 + h]);
    e[idx] = v;
    atomicAdd(&segsum[dst * 4 + h], v);
}

template <int C>
__global__ void aggregate_kernel(
    const float* __restrict__ xl, const float* __restrict__ e,
    const int* __restrict__ ei, const float* __restrict__ segsum,
    float* __restrict__ out)
{
    const int H = 4;
    int wg = (int)(((size_t)blockIdx.x * blockDim.x + threadIdx.x) >> 5);
    int lane = threadIdx.x & 31;
    if (wg >= NEDGE * H) return;
    int edge = wg >> 2;
    int h = wg & 3;
    int src = ei[edge];
    int dst = ei[NEDGE + edge];
    float alpha = e[edge * H + h] / (segsum[dst * H + h] + 1e-16f);
    const float* xls = xl + (size_t)src * (H * C) + h * C;
    float* od = out + (size_t)dst * (H * C) + h * C;
#pragma unroll
    for (int c = lane; c < C; c += 32)
        atomicAdd(&od[c], alpha * xls[c]);
}

__global__ void bn_stats_kernel(
    const float* __restrict__ h, const float* __restrict__ bias,
    int n, int C, float* __restrict__ sums)
{
    int c = threadIdx.x;
    float b = bias ? bias[c] : 0.0f;
    int r0 = blockIdx.x * 64;
    int r1 = min(r0 + 64, n);
    float s = 0.0f, s2 = 0.0f;
    for (int r = r0; r < r1; r++) {
        float v = h[(size_t)r * C + c] + b;
        s += v;
        s2 += v * v;
    }
    atomicAdd(&sums[c], s);
    atomicAdd(&sums[C + c], s2);
}

__global__ void bn_apply_elu_kernel(
    float* __restrict__ h, const float* __restrict__ bias,
    const float* __restrict__ sums, const float* __restrict__ g,
    const float* __restrict__ b, int n, int C)
{
    size_t total = (size_t)n * C;
    size_t i = (size_t)blockIdx.x * blockDim.x + threadIdx.x;
    size_t stride = (size_t)gridDim.x * blockDim.x;
    float inv_n = 1.0f / n;
    for (; i < total; i += stride) {
        int c = (int)(i % C);
        float mu = sums[c] * inv_n;
        float var = sums[C + c] * inv_n - mu * mu;
        float v = h[i] + (bias ? bias[c] : 0.0f);
        v = (v - mu) * rsqrtf(var + BN_EPS) * g[c] + b[c];
        h[i] = v > 0.0f ? v : expm1f(v);
    }
}

__global__ void head_mean_kernel(const float* __restrict__ agg, float* __restrict__ h1)
{
    int idx = blockIdx.x * blockDim.x + threadIdx.x;
    if (idx >= NNODE * C1) return;
    int node = idx >> 6;
    int c = idx & 63;
    const float* a = agg + (size_t)node * D1;
    h1[idx] = 0.25f * (a[c] + a[64 + c] + a[128 + c] + a[192 + c]);
}

__global__ void pool_kernel(
    const float* __restrict__ h1, const int* __restrict__ batch,
    float* __restrict__ pool, float* __restrict__ cnt)
{
    int idx = blockIdx.x * blockDim.x + threadIdx.x;
    if (idx >= NNODE * 64) return;
    int node = idx >> 6;
    int c = idx & 63;
    int b = batch[node];
    atomicAdd(&pool[b * 64 + c], h1[idx]);
    if (c == 0) atomicAdd(&cnt[b], 1.0f);
}

__global__ __launch_bounds__(256) void classifier_kernel(
    const float* __restrict__ pool, const float* __restrict__ cnt,
    const float* __restrict__ w1, const float* __restrict__ b1,
    const float* __restrict__ bn1g, const float* __restrict__ bn1b,
    const float* __restrict__ w2, const float* __restrict__ b2,
    const float* __restrict__ bn2g, const float* __restrict__ bn2b,
    const float* __restrict__ w3, const float* __restrict__ b3,
    float* __restrict__ z1, float* __restrict__ z2,
    float* __restrict__ out, int out_size)
{
    __shared__ float emb[64 * 64];
    __shared__ float sc1[256], sh1[256];
    __shared__ float sc2[128], sh2[128];
    int tid = threadIdx.x;

    for (int i = tid; i < 64 * 64; i += 256) {
        int b = i >> 6;
        emb[i] = pool[i] / fmaxf(cnt[b], 1.0f);
    }
    __syncthreads();

    if (out_size >= 4224) {
        for (int i = tid; i < 4096; i += 256) out[128 + i] = emb[i];
    }

    for (int i = tid; i < 64 * 256; i += 256) {
        int b = i >> 8, j = i & 255;
        float s = b1[j];
        const float* er = emb + b * 64;
        for (int k = 0; k < 64; k++) s = fmaf(er[k], w1[k * 256 + j], s);
        z1[i] = s;
    }
    __syncthreads();

    if (tid < 256) {
        float s = 0.f, s2 = 0.f;
        for (int b = 0; b < 64; b++) {
            float v = z1[b * 256 + tid];
            s += v; s2 += v * v;
        }
        float mu = s / 64.f;
        float var = s2 / 64.f - mu * mu;
        float sc = rsqrtf(var + BN_EPS) * bn1g[tid];
        sc1[tid] = sc;
        sh1[tid] = bn1b[tid] - mu * sc;
    }
    __syncthreads();
    for (int i = tid; i < 64 * 256; i += 256) {
        float v = z1[i] * sc1[i & 255] + sh1[i & 255];
        z1[i] = v > 0.f ? v : expm1f(v);
    }
    __syncthreads();

    for (int i = tid; i < 64 * 128; i += 256) {
        int b = i >> 7, j = i & 127;
        float s = b2[j];
        const float* zr = z1 + b * 256;
        for (int k = 0; k < 256; k++) s = fmaf(zr[k], w2[k * 128 + j], s);
        z2[i] = s;
    }
    __syncthreads();

    if (tid < 128) {
        float s = 0.f, s2 = 0.f;
        for (int b = 0; b < 64; b++) {
            float v = z2[b * 128 + tid];
            s += v; s2 += v * v;
        }
        float mu = s / 64.f;
        float var = s2 / 64.f - mu * mu;
        float sc = rsqrtf(var + BN_EPS) * bn2g[tid];
        sc2[tid] = sc;
        sh2[tid] = bn2b[tid] - mu * sc;
    }
    __syncthreads();
    for (int i = tid; i < 64 * 128; i += 256) {
        float v = z2[i] * sc2[i & 127] + sh2[i & 127];
        z2[i] = v > 0.f ? v : expm1f(v);
    }
    __syncthreads();

    if (tid < 128) {
        int b = tid >> 1, j = tid & 1;
        float s = b3[j];
        const float* zr = z2 + b * 128;
        for (int k = 0; k < 128; k++) s = fmaf(zr[k], w3[k * 2 + j], s);
        if (out_size >= 128) out[b * 2 + j] = s;
    }
}

// ================= launch =================
extern "C" void kernel_launch(void* const* d_in, const int* in_sizes, int n_in,
                              void* d_out, int out_size)
{
    const float* x       = (const float*)d_in[0];
    const int*   ei      = (const int*)d_in[1];
    const float* ea      = (const float*)d_in[2];
    const int*   bat     = (const int*)d_in[3];
    const float* g0_wl   = (const float*)d_in[4];
    const float* g0_wr   = (const float*)d_in[5];
    const float* g0_we   = (const float*)d_in[6];
    const float* g0_att  = (const float*)d_in[7];
    const float* g0_bias = (const float*)d_in[8];
    const float* bn0_g   = (const float*)d_in[9];
    const float* bn0_b   = (const float*)d_in[10];
    const float* g1_wl   = (const float*)d_in[11];
    const float* g1_wr   = (const float*)d_in[12];
    const float* g1_we   = (const float*)d_in[13];
    const float* g1_att  = (const float*)d_in[14];
    const float* g1_bias = (const float*)d_in[15];
    const float* bn1_g   = (const float*)d_in[16];
    const float* bn1_b   = (const float*)d_in[17];
    const float* c_w1    = (const float*)d_in[18];
    const float* c_b1    = (const float*)d_in[19];
    const float* cbn1_g  = (const float*)d_in[20];
    const float* cbn1_b  = (const float*)d_in[21];
    const float* c_w2    = (const float*)d_in[22];
    const float* c_b2    = (const float*)d_in[23];
    const float* cbn2_g  = (const float*)d_in[24];
    const float* cbn2_b  = (const float*)d_in[25];
    const float* c_w3    = (const float*)d_in[26];
    const float* c_b3    = (const float*)d_in[27];
    float* out = (float*)d_out;

    float* S = nullptr;
    cudaGetSymbolAddress((void**)&S, g_scratch);
    __nv_bfloat16* BF = nullptr;
    cudaGetSymbolAddress((void**)&BF, g_bf);

    float* xl0  = S + OFF_XL0;
    float* xr0  = S + OFF_XR0;
    float* h0   = S + OFF_H0;
    float* xl1  = S + OFF_XL1;
    float* xr1  = S + OFF_XR1;
    float* agg1 = S + OFF_AGG1;
    float* h1   = S + OFF_H1;
    float* e    = S + OFF_E;
    float* smax = S + OFF_SMAX;
    float* ssum = S + OFF_SSUM;
    float* bns  = S + OFF_BNS;
    float* pool = S + OFF_POOL;
    float* cnt  = S + OFF_CNT;
    float* z1   = S + OFF_Z1;
    float* z2   = S + OFF_Z2;

    __nv_bfloat16* A0h = BF + BF_A0;
    __nv_bfloat16* A0l = A0h + (size_t)MPAD * INDIM;
    __nv_bfloat16* A1h = BF + BF_A1;
    __nv_bfloat16* A1l = A1h + (size_t)MPAD * D0;
    __nv_bfloat16* B0lh = BF + BF_B0L;
    __nv_bfloat16* B0ll = B0lh + (size_t)D0 * INDIM;
    __nv_bfloat16* B0rh = BF + BF_B0R;
    __nv_bfloat16* B0rl = B0rh + (size_t)D0 * INDIM;
    __nv_bfloat16* B1lh = BF + BF_B1L;
    __nv_bfloat16* B1ll = B1lh + (size_t)D1 * D0;
    __nv_bfloat16* B1rh = BF + BF_B1R;
    __nv_bfloat16* B1rl = B1rh + (size_t)D1 * D0;

    cudaFuncSetAttribute(mma_gemm_kernel, cudaFuncAttributeMaxDynamicSharedMemorySize, GEMM_SMEM);

    const int warpBlocks = (NEDGE * 4 * 32) / 256;
    const int ehBlocks   = (NEDGE * 4 + 255) / 256;

    // ---- layer 0 init ----
    fill_kernel<<<4096, 256>>>(h0, 0.0f, (size_t)NNODE * D0);
    fill_kernel<<<256, 256>>>(ssum, 0.0f, (size_t)NNODE * 4);
    fill_kernel<<<256, 256>>>(smax, -INFINITY, (size_t)NNODE * 4);
    fill_kernel<<<4, 256>>>(bns, 0.0f, 1024);
    fill_kernel<<<17, 256>>>(pool, 0.0f, 64 * 64 + 64);

    // ---- layer 0 GEMMs (bf16x3 mma.sync) ----
    convA_kernel<<<(MPAD * INDIM / 4 + 255) / 256, 256>>>(x, A0h, A0l, NNODE, MPAD, INDIM);
    convB_kernel<<<(D0 * INDIM + 255) / 256, 256>>>(g0_wl, B0lh, B0ll, INDIM, D0);
    convB_kernel<<<(D0 * INDIM + 255) / 256, 256>>>(g0_wr, B0rh, B0rl, INDIM, D0);
    {
        dim3 gg(D0 / 128, NMT);
        mma_gemm_kernel<<<gg, 256, GEMM_SMEM>>>(A0h, A0l, B0lh, B0ll, xl0, NNODE, D0, INDIM);
        mma_gemm_kernel<<<gg, 256, GEMM_SMEM>>>(A0h, A0l, B0rh, B0rl, xr0, NNODE, D0, INDIM);
    }

    edge_score_kernel<C0><<<warpBlocks, 256>>>(xl0, xr0, ei, ea, g0_we, g0_att, e, smax);
    edge_exp_kernel<<<ehBlocks, 256>>>(e, ei, smax, ssum);
    aggregate_kernel<C0><<<warpBlocks, 256>>>(xl0, e, ei, ssum, h0);
    bn_stats_kernel<<<(NNODE + 63) / 64, D0>>>(h0, g0_bias, NNODE, D0, bns);
    bn_apply_elu_kernel<<<2048, 256>>>(h0, g0_bias, bns, bn0_g, bn0_b, NNODE, D0);

    // ---- layer 1 init ----
    fill_kernel<<<2048, 256>>>(agg1, 0.0f, (size_t)NNODE * D1);
    fill_kernel<<<256, 256>>>(ssum, 0.0f, (size_t)NNODE * 4);
    fill_kernel<<<256, 256>>>(smax, -INFINITY, (size_t)NNODE * 4);
    fill_kernel<<<4, 256>>>(bns, 0.0f, 1024);

    // ---- layer 1 GEMMs ----
    convA_kernel<<<(MPAD * D0 / 4 + 255) / 256, 256>>>(h0, A1h, A1l, NNODE, MPAD, D0);
    convB_kernel<<<(D1 * D0 + 255) / 256, 256>>>(g1_wl, B1lh, B1ll, D0, D1);
    convB_kernel<<<(D1 * D0 + 255) / 256, 256>>>(g1_wr, B1rh, B1rl, D0, D1);
    {
        dim3 gg(D1 / 128, NMT);
        mma_gemm_kernel<<<gg, 256, GEMM_SMEM>>>(A1h, A1l, B1lh, B1ll, xl1, NNODE, D1, D0);
        mma_gemm_kernel<<<gg, 256, GEMM_SMEM>>>(A1h, A1l, B1rh, B1rl, xr1, NNODE, D1, D0);
    }

    edge_score_kernel<C1><<<warpBlocks, 256>>>(xl1, xr1, ei, ea, g1_we, g1_att, e, smax);
    edge_exp_kernel<<<ehBlocks, 256>>>(e, ei, smax, ssum);
    aggregate_kernel<C1><<<warpBlocks, 256>>>(xl1, e, ei, ssum, agg1);
    head_mean_kernel<<<(NNODE * C1 + 255) / 256, 256>>>(agg1, h1);
    bn_stats_kernel<<<(NNODE + 63) / 64, C1>>>(h1, g1_bias, NNODE, C1, bns);
    bn_apply_elu_kernel<<<1024, 256>>>(h1, g1_bias, bns, bn1_g, bn1_b, NNODE, C1);

    // ---- pool + classifier ----
    pool_kernel<<<(NNODE * 64 + 255) / 256, 256>>>(h1, bat, pool, cnt);
    classifier_kernel<<<1, 256>>>(pool, cnt,
                                  c_w1, c_b1, cbn1_g, cbn1_b,
                                  c_w2, c_b2, cbn2_g, cbn2_b,
                                  c_w3, c_b3, z1, z2, out, out_size);
}

// round 5
// speedup vs baseline: 2.0795x; 1.5204x over previous
#include <cuda_runtime.h>
#include <cuda_bf16.h>
#include <math.h>
#include <stdint.h>

// Problem constants
#define NNODE 20000
#define NEDGE 320000
#define INDIM 256
#define NB 64
#define H0 4
#define C0 128
#define D0 512   // H0*C0
#define H1 4
#define C1 64
#define D1 256   // H1*C1
#define NEG_SLOPE 0.2f
#define BN_EPS 1e-5f

#define MPAD 20096   // 157 * 128
#define NMT 157

// ---------------- fp32 scratch layout (floats) ----------------
#define OFF_XL0  ((size_t)0)
#define OFF_XR0  ((size_t)10240000)
#define OFF_H0   ((size_t)20480000)
#define OFF_XL1  ((size_t)30720000)
#define OFF_XR1  ((size_t)35840000)
#define OFF_AGG1 ((size_t)40960000)
#define OFF_H1   ((size_t)46080000)
#define OFF_BNS  ((size_t)48800000)
#define OFF_POOL ((size_t)48801024)
#define OFF_CNT  ((size_t)48805120)
#define OFF_Z1   ((size_t)48805184)
#define OFF_Z2   ((size_t)48821568)
#define SCRATCH_FLOATS ((size_t)48829760)

__device__ __align__(256) float g_scratch[SCRATCH_FLOATS];

// ---------------- CSR scratch ----------------
__device__ int   g_cnt[NNODE];
__device__ int   g_indptr[NNODE + 1];
__device__ int   g_srccsr[NEDGE];
__device__ float g_eacsr[NEDGE];

// ---------------- bf16 operand scratch (hi/lo pairs) ----------------
#define BF_A0  ((size_t)0)
#define BF_A1  ((size_t)10289152)
#define BF_B0L ((size_t)30867456)
#define BF_B0R ((size_t)31129600)
#define BF_B1L ((size_t)31391744)
#define BF_B1R ((size_t)31653888)
#define BF_TOTAL ((size_t)31916032)

__device__ __align__(1024) __nv_bfloat16 g_bf[BF_TOTAL];

// ================= PTX helpers (portable sm_80+ only) =================
__device__ __forceinline__ uint32_t smem_to_u32(const void* p) {
    uint32_t a;
    asm("{ .reg .u64 t; cvta.to.shared.u64 t, %1; cvt.u32.u64 %0, t; }" : "=r"(a) : "l"(p));
    return a;
}
__device__ __forceinline__ void ldsm_x4(uint32_t* r, uint32_t addr) {
    asm volatile("ldmatrix.sync.aligned.m8n8.x4.shared.b16 {%0,%1,%2,%3}, [%4];"
        : "=r"(r[0]), "=r"(r[1]), "=r"(r[2]), "=r"(r[3]) : "r"(addr));
}
__device__ __forceinline__ void ldsm_x2(uint32_t* r, uint32_t addr) {
    asm volatile("ldmatrix.sync.aligned.m8n8.x2.shared.b16 {%0,%1}, [%2];"
        : "=r"(r[0]), "=r"(r[1]) : "r"(addr));
}
__device__ __forceinline__ void mma_bf16(float* d, const uint32_t* a, const uint32_t* b) {
    asm volatile(
        "mma.sync.aligned.m16n8k16.row.col.f32.bf16.bf16.f32 "
        "{%0,%1,%2,%3}, {%4,%5,%6,%7}, {%8,%9}, {%0,%1,%2,%3};"
        : "+f"(d[0]), "+f"(d[1]), "+f"(d[2]), "+f"(d[3])
        : "r"(a[0]), "r"(a[1]), "r"(a[2]), "r"(a[3]), "r"(b[0]), "r"(b[1]));
}

// ================= operand conversion =================
__global__ void convA_kernel(const float* __restrict__ A, __nv_bfloat16* __restrict__ hi,
                             __nv_bfloat16* __restrict__ lo, int Mreal, int Mpad, int K) {
    size_t i4 = (size_t)blockIdx.x * blockDim.x + threadIdx.x;
    size_t total = (size_t)Mpad * K / 4;
    if (i4 >= total) return;
    size_t base = i4 * 4;
    int row = (int)(base / K);
    float4 v = make_float4(0.f, 0.f, 0.f, 0.f);
    if (row < Mreal) v = *(const float4*)(A + base);
    float a[4] = {v.x, v.y, v.z, v.w};
    __nv_bfloat16 h[4], l[4];
#pragma unroll
    for (int j = 0; j < 4; j++) {
        h[j] = __float2bfloat16(a[j]);
        l[j] = __float2bfloat16(a[j] - __bfloat162float(h[j]));
    }
    __nv_bfloat162* hp = (__nv_bfloat162*)(hi + base);
    __nv_bfloat162* lp = (__nv_bfloat162*)(lo + base);
    __nv_bfloat162 t;
    t.x = h[0]; t.y = h[1]; hp[0] = t;
    t.x = h[2]; t.y = h[3]; hp[1] = t;
    t.x = l[0]; t.y = l[1]; lp[0] = t;
    t.x = l[2]; t.y = l[3]; lp[1] = t;
}

__global__ void convB_kernel(const float* __restrict__ W, __nv_bfloat16* __restrict__ hi,
                             __nv_bfloat16* __restrict__ lo, int K, int N) {
    int idx = blockIdx.x * blockDim.x + threadIdx.x;
    if (idx >= N * K) return;
    int n = idx / K, k = idx % K;
    float a = W[(size_t)k * N + n];
    __nv_bfloat16 h = __float2bfloat16(a);
    hi[idx] = h;
    lo[idx] = __float2bfloat16(a - __bfloat162float(h));
}

// ================= bf16x3 mma.sync GEMM =================
#define LDA 72
__global__ __launch_bounds__(256) void mma_gemm_kernel(
    const __nv_bfloat16* __restrict__ Ah, const __nv_bfloat16* __restrict__ Al,
    const __nv_bfloat16* __restrict__ Bh, const __nv_bfloat16* __restrict__ Bl,
    float* __restrict__ C, int Mreal, int N, int K)
{
    extern __shared__ __align__(16) char smem[];
    __nv_bfloat16* sAh = (__nv_bfloat16*)smem;
    __nv_bfloat16* sAl = sAh + 128 * LDA;
    __nv_bfloat16* sBh = sAl + 128 * LDA;
    __nv_bfloat16* sBl = sBh + 128 * LDA;
    uint32_t sbase = smem_to_u32(smem);
    const uint32_t oAh = 0;
    const uint32_t oAl = 128 * LDA * 2;
    const uint32_t oBh = 2 * 128 * LDA * 2;
    const uint32_t oBl = 3 * 128 * LDA * 2;

    int tid = threadIdx.x, wid = tid >> 5, lane = tid & 31;
    int mt = blockIdx.y, nt = blockIdx.x;
    int wm = wid >> 2;
    int wn = wid & 3;

    float acc[4][4][4];
#pragma unroll
    for (int i = 0; i < 4; i++)
#pragma unroll
        for (int j = 0; j < 4; j++)
#pragma unroll
            for (int q = 0; q < 4; q++) acc[i][j][q] = 0.f;

    const int chunk = tid & 7;
    const int row4  = tid >> 3;

    for (int k0 = 0; k0 < K; k0 += 64) {
#pragma unroll
        for (int p = 0; p < 4; p++) {
            int r = row4 + p * 32;
            size_t ga = (size_t)(mt * 128 + r) * K + k0 + chunk * 8;
            size_t gb = (size_t)(nt * 128 + r) * K + k0 + chunk * 8;
            *(uint4*)(sAh + r * LDA + chunk * 8) = *(const uint4*)(Ah + ga);
            *(uint4*)(sAl + r * LDA + chunk * 8) = *(const uint4*)(Al + ga);
            *(uint4*)(sBh + r * LDA + chunk * 8) = *(const uint4*)(Bh + gb);
            *(uint4*)(sBl + r * LDA + chunk * 8) = *(const uint4*)(Bl + gb);
        }
        __syncthreads();

#pragma unroll
        for (int ks = 0; ks < 4; ks++) {
            uint32_t ah[4][4], al[4][4], bh[4][2], bl[4][2];
            uint32_t arow = (uint32_t)(wm * 64 + (lane & 15));
            uint32_t acol = (uint32_t)(ks * 16 + (lane >> 4) * 8);
#pragma unroll
            for (int i = 0; i < 4; i++) {
                uint32_t off = ((arow + i * 16) * LDA + acol) * 2;
                ldsm_x4(ah[i], sbase + oAh + off);
                ldsm_x4(al[i], sbase + oAl + off);
            }
            uint32_t brow = (uint32_t)(wn * 32 + (lane & 7));
            uint32_t bcol = (uint32_t)(ks * 16 + ((lane >> 3) & 1) * 8);
#pragma unroll
            for (int j = 0; j < 4; j++) {
                uint32_t off = ((brow + j * 8) * LDA + bcol) * 2;
                ldsm_x2(bh[j], sbase + oBh + off);
                ldsm_x2(bl[j], sbase + oBl + off);
            }
#pragma unroll
            for (int i = 0; i < 4; i++)
#pragma unroll
                for (int j = 0; j < 4; j++) {
                    mma_bf16(acc[i][j], ah[i], bh[j]);
                    mma_bf16(acc[i][j], ah[i], bl[j]);
                    mma_bf16(acc[i][j], al[i], bh[j]);
                }
        }
        __syncthreads();
    }

#pragma unroll
    for (int i = 0; i < 4; i++) {
        int r0 = mt * 128 + wm * 64 + i * 16 + (lane >> 2);
        int r1 = r0 + 8;
#pragma unroll
        for (int j = 0; j < 4; j++) {
            int c = nt * 128 + wn * 32 + j * 8 + (lane & 3) * 2;
            if (r0 < Mreal)
                *(float2*)(C + (size_t)r0 * N + c) = make_float2(acc[i][j][0], acc[i][j][1]);
            if (r1 < Mreal)
                *(float2*)(C + (size_t)r1 * N + c) = make_float2(acc[i][j][2], acc[i][j][3]);
        }
    }
}
#define GEMM_SMEM (4 * 128 * LDA * 2)

// ================= CSR construction =================
__global__ void zero_int_kernel(int* p, int n) {
    int i = blockIdx.x * blockDim.x + threadIdx.x;
    if (i < n) p[i] = 0;
}

__global__ void hist_kernel(const int* __restrict__ ei, int* __restrict__ cnt) {
    int i = blockIdx.x * blockDim.x + threadIdx.x;
    if (i < NEDGE) atomicAdd(&cnt[ei[NEDGE + i]], 1);
}

// one-block exclusive scan of cnt[0..n) -> indptr, indptr[n]=total
__global__ __launch_bounds__(1024) void scan_kernel(const int* __restrict__ cnt,
                                                    int* __restrict__ indptr, int n) {
    __shared__ int part[1024];
    int tid = threadIdx.x;
    int chunk = (n + 1023) / 1024;
    int base = tid * chunk;
    int s = 0;
    for (int i = 0; i < chunk; i++)
        if (base + i < n) s += cnt[base + i];
    part[tid] = s;
    __syncthreads();
    // Hillis-Steele inclusive scan
    for (int off = 1; off < 1024; off <<= 1) {
        int v = (tid >= off) ? part[tid - off] : 0;
        __syncthreads();
        part[tid] += v;
        __syncthreads();
    }
    int run = (tid == 0) ? 0 : part[tid - 1];
    for (int i = 0; i < chunk; i++) {
        if (base + i < n) {
            indptr[base + i] = run;
            run += cnt[base + i];
        }
    }
    if (tid == 1023) indptr[n] = part[1023];
}

__global__ void scatter_kernel(const int* __restrict__ ei, const float* __restrict__ ea,
                               const int* __restrict__ indptr, int* __restrict__ fill,
                               int* __restrict__ srccsr, float* __restrict__ eacsr) {
    int i = blockIdx.x * blockDim.x + threadIdx.x;
    if (i >= NEDGE) return;
    int dst = ei[NEDGE + i];
    int pos = indptr[dst] + atomicAdd(&fill[dst], 1);
    srccsr[pos] = ei[i];
    eacsr[pos] = ea[i];
}

// ================= fused GATv2 (online softmax, warp per (dst, head)) =================
template <int C>
__global__ void gat_fused_kernel(
    const float* __restrict__ xl, const float* __restrict__ xr,
    const int* __restrict__ indptr, const int* __restrict__ srccsr,
    const float* __restrict__ eacsr,
    const float* __restrict__ we, const float* __restrict__ att,
    float* __restrict__ out)
{
    const int H = 4, D = 4 * C, CH = C / 32;
    int wg = (blockIdx.x * blockDim.x + threadIdx.x) >> 5;
    int lane = threadIdx.x & 31;
    if (wg >= NNODE * H) return;
    int dst = wg >> 2, h = wg & 3;
    int p0 = indptr[dst], p1 = indptr[dst + 1];

    float xr_r[CH], we_r[CH], att_r[CH];
    const float* xrd = xr + (size_t)dst * D + h * C;
#pragma unroll
    for (int j = 0; j < CH; j++) {
        int c = lane + j * 32;
        xr_r[j]  = xrd[c];
        we_r[j]  = we[h * C + c];
        att_r[j] = att[h * C + c];
    }

    float maxv = -INFINITY, denom = 0.f;
    float acc[CH];
#pragma unroll
    for (int j = 0; j < CH; j++) acc[j] = 0.f;

    for (int p = p0; p < p1; p++) {
        int src = srccsr[p];
        float eav = eacsr[p];
        const float* xls = xl + (size_t)src * D + h * C;
        float xv[CH];
        float s = 0.f;
#pragma unroll
        for (int j = 0; j < CH; j++) {
            xv[j] = xls[lane + j * 32];
            float m = xv[j] + xr_r[j] + eav * we_r[j];
            m = m > 0.f ? m : NEG_SLOPE * m;
            s = fmaf(m, att_r[j], s);
        }
#pragma unroll
        for (int o = 16; o; o >>= 1) s += __shfl_xor_sync(0xffffffff, s, o);
        // online softmax update
        float mnew = fmaxf(maxv, s);
        float corr = expf(maxv - mnew);   // exp(-inf)=0 on first edge
        float w = expf(s - mnew);
        denom = denom * corr + w;
#pragma unroll
        for (int j = 0; j < CH; j++) acc[j] = fmaf(acc[j], corr, w * xv[j]);
        maxv = mnew;
    }

    float inv = 1.f / (denom + 1e-16f);
    float* od = out + (size_t)dst * D + h * C;
#pragma unroll
    for (int j = 0; j < CH; j++) od[lane + j * 32] = acc[j] * inv;
}

// ================= misc =================
__global__ void fill_kernel(float* p, float v, size_t n) {
    size_t i = (size_t)blockIdx.x * blockDim.x + threadIdx.x;
    size_t stride = (size_t)gridDim.x * blockDim.x;
    for (; i < n; i += stride) p[i] = v;
}

__global__ void bn_stats_kernel(
    const float* __restrict__ h, const float* __restrict__ bias,
    int n, int C, float* __restrict__ sums)
{
    int c = threadIdx.x;
    float b = bias ? bias[c] : 0.0f;
    int r0 = blockIdx.x * 64;
    int r1 = min(r0 + 64, n);
    float s = 0.0f, s2 = 0.0f;
    for (int r = r0; r < r1; r++) {
        float v = h[(size_t)r * C + c] + b;
        s += v;
        s2 += v * v;
    }
    atomicAdd(&sums[c], s);
    atomicAdd(&sums[C + c], s2);
}

__global__ void bn_apply_elu_kernel(
    float* __restrict__ h, const float* __restrict__ bias,
    const float* __restrict__ sums, const float* __restrict__ g,
    const float* __restrict__ b, int n, int C)
{
    size_t total = (size_t)n * C;
    size_t i = (size_t)blockIdx.x * blockDim.x + threadIdx.x;
    size_t stride = (size_t)gridDim.x * blockDim.x;
    float inv_n = 1.0f / n;
    for (; i < total; i += stride) {
        int c = (int)(i % C);
        float mu = sums[c] * inv_n;
        float var = sums[C + c] * inv_n - mu * mu;
        float v = h[i] + (bias ? bias[c] : 0.0f);
        v = (v - mu) * rsqrtf(var + BN_EPS) * g[c] + b[c];
        h[i] = v > 0.0f ? v : expm1f(v);
    }
}

__global__ void head_mean_kernel(const float* __restrict__ agg, float* __restrict__ h1)
{
    int idx = blockIdx.x * blockDim.x + threadIdx.x;
    if (idx >= NNODE * C1) return;
    int node = idx >> 6;
    int c = idx & 63;
    const float* a = agg + (size_t)node * D1;
    h1[idx] = 0.25f * (a[c] + a[64 + c] + a[128 + c] + a[192 + c]);
}

__global__ void pool_kernel(
    const float* __restrict__ h1, const int* __restrict__ batch,
    float* __restrict__ pool, float* __restrict__ cnt)
{
    int idx = blockIdx.x * blockDim.x + threadIdx.x;
    if (idx >= NNODE * 64) return;
    int node = idx >> 6;
    int c = idx & 63;
    int b = batch[node];
    atomicAdd(&pool[b * 64 + c], h1[idx]);
    if (c == 0) atomicAdd(&cnt[b], 1.0f);
}

__global__ __launch_bounds__(256) void classifier_kernel(
    const float* __restrict__ pool, const float* __restrict__ cnt,
    const float* __restrict__ w1, const float* __restrict__ b1,
    const float* __restrict__ bn1g, const float* __restrict__ bn1b,
    const float* __restrict__ w2, const float* __restrict__ b2,
    const float* __restrict__ bn2g, const float* __restrict__ bn2b,
    const float* __restrict__ w3, const float* __restrict__ b3,
    float* __restrict__ z1, float* __restrict__ z2,
    float* __restrict__ out, int out_size)
{
    __shared__ float emb[64 * 64];
    __shared__ float sc1[256], sh1[256];
    __shared__ float sc2[128], sh2[128];
    int tid = threadIdx.x;

    for (int i = tid; i < 64 * 64; i += 256) {
        int b = i >> 6;
        emb[i] = pool[i] / fmaxf(cnt[b], 1.0f);
    }
    __syncthreads();

    if (out_size >= 4224) {
        for (int i = tid; i < 4096; i += 256) out[128 + i] = emb[i];
    }

    for (int i = tid; i < 64 * 256; i += 256) {
        int b = i >> 8, j = i & 255;
        float s = b1[j];
        const float* er = emb + b * 64;
        for (int k = 0; k < 64; k++) s = fmaf(er[k], w1[k * 256 + j], s);
        z1[i] = s;
    }
    __syncthreads();

    if (tid < 256) {
        float s = 0.f, s2 = 0.f;
        for (int b = 0; b < 64; b++) {
            float v = z1[b * 256 + tid];
            s += v; s2 += v * v;
        }
        float mu = s / 64.f;
        float var = s2 / 64.f - mu * mu;
        float sc = rsqrtf(var + BN_EPS) * bn1g[tid];
        sc1[tid] = sc;
        sh1[tid] = bn1b[tid] - mu * sc;
    }
    __syncthreads();
    for (int i = tid; i < 64 * 256; i += 256) {
        float v = z1[i] * sc1[i & 255] + sh1[i & 255];
        z1[i] = v > 0.f ? v : expm1f(v);
    }
    __syncthreads();

    for (int i = tid; i < 64 * 128; i += 256) {
        int b = i >> 7, j = i & 127;
        float s = b2[j];
        const float* zr = z1 + b * 256;
        for (int k = 0; k < 256; k++) s = fmaf(zr[k], w2[k * 128 + j], s);
        z2[i] = s;
    }
    __syncthreads();

    if (tid < 128) {
        float s = 0.f, s2 = 0.f;
        for (int b = 0; b < 64; b++) {
            float v = z2[b * 128 + tid];
            s += v; s2 += v * v;
        }
        float mu = s / 64.f;
        float var = s2 / 64.f - mu * mu;
        float sc = rsqrtf(var + BN_EPS) * bn2g[tid];
        sc2[tid] = sc;
        sh2[tid] = bn2b[tid] - mu * sc;
    }
    __syncthreads();
    for (int i = tid; i < 64 * 128; i += 256) {
        float v = z2[i] * sc2[i & 127] + sh2[i & 127];
        z2[i] = v > 0.f ? v : expm1f(v);
    }
    __syncthreads();

    if (tid < 128) {
        int b = tid >> 1, j = tid & 1;
        float s = b3[j];
        const float* zr = z2 + b * 128;
        for (int k = 0; k < 128; k++) s = fmaf(zr[k], w3[k * 2 + j], s);
        if (out_size >= 128) out[b * 2 + j] = s;
    }
}

// ================= launch =================
extern "C" void kernel_launch(void* const* d_in, const int* in_sizes, int n_in,
                              void* d_out, int out_size)
{
    const float* x       = (const float*)d_in[0];
    const int*   ei      = (const int*)d_in[1];
    const float* ea      = (const float*)d_in[2];
    const int*   bat     = (const int*)d_in[3];
    const float* g0_wl   = (const float*)d_in[4];
    const float* g0_wr   = (const float*)d_in[5];
    const float* g0_we   = (const float*)d_in[6];
    const float* g0_att  = (const float*)d_in[7];
    const float* g0_bias = (const float*)d_in[8];
    const float* bn0_g   = (const float*)d_in[9];
    const float* bn0_b   = (const float*)d_in[10];
    const float* g1_wl   = (const float*)d_in[11];
    const float* g1_wr   = (const float*)d_in[12];
    const float* g1_we   = (const float*)d_in[13];
    const float* g1_att  = (const float*)d_in[14];
    const float* g1_bias = (const float*)d_in[15];
    const float* bn1_g   = (const float*)d_in[16];
    const float* bn1_b   = (const float*)d_in[17];
    const float* c_w1    = (const float*)d_in[18];
    const float* c_b1    = (const float*)d_in[19];
    const float* cbn1_g  = (const float*)d_in[20];
    const float* cbn1_b  = (const float*)d_in[21];
    const float* c_w2    = (const float*)d_in[22];
    const float* c_b2    = (const float*)d_in[23];
    const float* cbn2_g  = (const float*)d_in[24];
    const float* cbn2_b  = (const float*)d_in[25];
    const float* c_w3    = (const float*)d_in[26];
    const float* c_b3    = (const float*)d_in[27];
    float* out = (float*)d_out;

    float* S = nullptr;
    cudaGetSymbolAddress((void**)&S, g_scratch);
    __nv_bfloat16* BF = nullptr;
    cudaGetSymbolAddress((void**)&BF, g_bf);
    int* csr_cnt = nullptr;    cudaGetSymbolAddress((void**)&csr_cnt, g_cnt);
    int* indptr = nullptr;     cudaGetSymbolAddress((void**)&indptr, g_indptr);
    int* srccsr = nullptr;     cudaGetSymbolAddress((void**)&srccsr, g_srccsr);
    float* eacsr = nullptr;    cudaGetSymbolAddress((void**)&eacsr, g_eacsr);

    float* xl0  = S + OFF_XL0;
    float* xr0  = S + OFF_XR0;
    float* h0   = S + OFF_H0;
    float* xl1  = S + OFF_XL1;
    float* xr1  = S + OFF_XR1;
    float* agg1 = S + OFF_AGG1;
    float* h1   = S + OFF_H1;
    float* bns  = S + OFF_BNS;
    float* pool = S + OFF_POOL;
    float* cnt  = S + OFF_CNT;
    float* z1   = S + OFF_Z1;
    float* z2   = S + OFF_Z2;

    __nv_bfloat16* A0h = BF + BF_A0;
    __nv_bfloat16* A0l = A0h + (size_t)MPAD * INDIM;
    __nv_bfloat16* A1h = BF + BF_A1;
    __nv_bfloat16* A1l = A1h + (size_t)MPAD * D0;
    __nv_bfloat16* B0lh = BF + BF_B0L;
    __nv_bfloat16* B0ll = B0lh + (size_t)D0 * INDIM;
    __nv_bfloat16* B0rh = BF + BF_B0R;
    __nv_bfloat16* B0rl = B0rh + (size_t)D0 * INDIM;
    __nv_bfloat16* B1lh = BF + BF_B1L;
    __nv_bfloat16* B1ll = B1lh + (size_t)D1 * D0;
    __nv_bfloat16* B1rh = BF + BF_B1R;
    __nv_bfloat16* B1rl = B1rh + (size_t)D1 * D0;

    cudaFuncSetAttribute(mma_gemm_kernel, cudaFuncAttributeMaxDynamicSharedMemorySize, GEMM_SMEM);

    const int gatBlocks = (NNODE * 4 * 32 + 255) / 256;   // warp per (dst, head)

    // ---- CSR build (shared by both layers) ----
    zero_int_kernel<<<(NNODE + 255) / 256, 256>>>(csr_cnt, NNODE);
    hist_kernel<<<(NEDGE + 255) / 256, 256>>>(ei, csr_cnt);
    scan_kernel<<<1, 1024>>>(csr_cnt, indptr, NNODE);
    zero_int_kernel<<<(NNODE + 255) / 256, 256>>>(csr_cnt, NNODE);
    scatter_kernel<<<(NEDGE + 255) / 256, 256>>>(ei, ea, indptr, csr_cnt, srccsr, eacsr);

    // ---- small fills ----
    fill_kernel<<<4, 256>>>(bns, 0.0f, 1024);
    fill_kernel<<<17, 256>>>(pool, 0.0f, 64 * 64 + 64);

    // ---- layer 0 GEMMs (bf16x3 mma.sync) ----
    convA_kernel<<<(MPAD * INDIM / 4 + 255) / 256, 256>>>(x, A0h, A0l, NNODE, MPAD, INDIM);
    convB_kernel<<<(D0 * INDIM + 255) / 256, 256>>>(g0_wl, B0lh, B0ll, INDIM, D0);
    convB_kernel<<<(D0 * INDIM + 255) / 256, 256>>>(g0_wr, B0rh, B0rl, INDIM, D0);
    {
        dim3 gg(D0 / 128, NMT);
        mma_gemm_kernel<<<gg, 256, GEMM_SMEM>>>(A0h, A0l, B0lh, B0ll, xl0, NNODE, D0, INDIM);
        mma_gemm_kernel<<<gg, 256, GEMM_SMEM>>>(A0h, A0l, B0rh, B0rl, xr0, NNODE, D0, INDIM);
    }

    // ---- layer 0 fused GAT ----
    gat_fused_kernel<C0><<<gatBlocks, 256>>>(xl0, xr0, indptr, srccsr, eacsr, g0_we, g0_att, h0);
    bn_stats_kernel<<<(NNODE + 63) / 64, D0>>>(h0, g0_bias, NNODE, D0, bns);
    bn_apply_elu_kernel<<<2048, 256>>>(h0, g0_bias, bns, bn0_g, bn0_b, NNODE, D0);

    // ---- layer 1 ----
    fill_kernel<<<4, 256>>>(bns, 0.0f, 1024);
    convA_kernel<<<(MPAD * D0 / 4 + 255) / 256, 256>>>(h0, A1h, A1l, NNODE, MPAD, D0);
    convB_kernel<<<(D1 * D0 + 255) / 256, 256>>>(g1_wl, B1lh, B1ll, D0, D1);
    convB_kernel<<<(D1 * D0 + 255) / 256, 256>>>(g1_wr, B1rh, B1rl, D0, D1);
    {
        dim3 gg(D1 / 128, NMT);
        mma_gemm_kernel<<<gg, 256, GEMM_SMEM>>>(A1h, A1l, B1lh, B1ll, xl1, NNODE, D1, D0);
        mma_gemm_kernel<<<gg, 256, GEMM_SMEM>>>(A1h, A1l, B1rh, B1rl, xr1, NNODE, D1, D0);
    }

    gat_fused_kernel<C1><<<gatBlocks, 256>>>(xl1, xr1, indptr, srccsr, eacsr, g1_we, g1_att, agg1);
    head_mean_kernel<<<(NNODE * C1 + 255) / 256, 256>>>(agg1, h1);
    bn_stats_kernel<<<(NNODE + 63) / 64, C1>>>(h1, g1_bias, NNODE, C1, bns);
    bn_apply_elu_kernel<<<1024, 256>>>(h1, g1_bias, bns, bn1_g, bn1_b, NNODE, C1);

    // ---- pool + classifier ----
    pool_kernel<<<(NNODE * 64 + 255) / 256, 256>>>(h1, bat, pool, cnt);
    classifier_kernel<<<1, 256>>>(pool, cnt,
                                  c_w1, c_b1, cbn1_g, cbn1_b,
                                  c_w2, c_b2, cbn2_g, cbn2_b,
                                  c_w3, c_b3, z1, z2, out, out_size);
}

// round 6
// speedup vs baseline: 2.1733x; 1.0451x over previous
#include <cuda_runtime.h>
#include <cuda_bf16.h>
#include <math.h>
#include <stdint.h>

// Problem constants
#define NNODE 20000
#define NEDGE 320000
#define INDIM 256
#define NB 64
#define H0 4
#define C0 128
#define D0 512   // H0*C0
#define H1 4
#define C1 64
#define D1 256   // H1*C1
#define NEG_SLOPE 0.2f
#define BN_EPS 1e-5f

#define MPAD 20096   // 157 * 128
#define NMT 157

// ---------------- fp32 scratch layout (floats) ----------------
#define OFF_XLR0 ((size_t)0)          // [NNODE x 1024]: xl0 cols 0-511, xr0 cols 512-1023
#define OFF_H0   ((size_t)20480000)   // [NNODE x 512]
#define OFF_XLR1 ((size_t)30720000)   // [NNODE x 512]: xl1 cols 0-255, xr1 cols 256-511
#define OFF_AGG1 ((size_t)40960000)   // [NNODE x 256]
#define OFF_H1   ((size_t)46080000)   // [NNODE x 64]
#define OFF_BNS  ((size_t)48800000)
#define OFF_POOL ((size_t)48801024)
#define OFF_CNT  ((size_t)48805120)
#define OFF_Z1   ((size_t)48805184)
#define OFF_Z2   ((size_t)48821568)
#define SCRATCH_FLOATS ((size_t)48829760)

__device__ __align__(256) float g_scratch[SCRATCH_FLOATS];

// ---------------- CSR scratch ----------------
__device__ int   g_cnt[NNODE];
__device__ int   g_indptr[NNODE + 1];
__device__ int   g_srccsr[NEDGE];
__device__ float g_eacsr[NEDGE];

// ---------------- bf16 weight scratch (transposed, hi/lo) ----------------
// B0: [1024 x 256] (wl rows 0-511, wr rows 512-1023), hi then lo
// B1: [512 x 512]  (wl rows 0-255, wr rows 256-511), hi then lo
#define BW_B0H ((size_t)0)
#define BW_B0L ((size_t)262144)
#define BW_B1H ((size_t)524288)
#define BW_B1L ((size_t)786432)
#define BW_TOTAL ((size_t)1048576)
__device__ __align__(1024) __nv_bfloat16 g_bw[BW_TOTAL];

// ================= PTX helpers (portable sm_80+ only) =================
__device__ __forceinline__ uint32_t smem_to_u32(const void* p) {
    uint32_t a;
    asm("{ .reg .u64 t; cvta.to.shared.u64 t, %1; cvt.u32.u64 %0, t; }" : "=r"(a) : "l"(p));
    return a;
}
__device__ __forceinline__ void ldsm_x4(uint32_t* r, uint32_t addr) {
    asm volatile("ldmatrix.sync.aligned.m8n8.x4.shared.b16 {%0,%1,%2,%3}, [%4];"
        : "=r"(r[0]), "=r"(r[1]), "=r"(r[2]), "=r"(r[3]) : "r"(addr));
}
__device__ __forceinline__ void ldsm_x2(uint32_t* r, uint32_t addr) {
    asm volatile("ldmatrix.sync.aligned.m8n8.x2.shared.b16 {%0,%1}, [%2];"
        : "=r"(r[0]), "=r"(r[1]) : "r"(addr));
}
__device__ __forceinline__ void mma_bf16(float* d, const uint32_t* a, const uint32_t* b) {
    asm volatile(
        "mma.sync.aligned.m16n8k16.row.col.f32.bf16.bf16.f32 "
        "{%0,%1,%2,%3}, {%4,%5,%6,%7}, {%8,%9}, {%0,%1,%2,%3};"
        : "+f"(d[0]), "+f"(d[1]), "+f"(d[2]), "+f"(d[3])
        : "r"(a[0]), "r"(a[1]), "r"(a[2]), "r"(a[3]), "r"(b[0]), "r"(b[1]));
}
__device__ __forceinline__ void cpasync16(uint32_t saddr, const void* gptr) {
    asm volatile("cp.async.cg.shared.global [%0], [%1], 16;" :: "r"(saddr), "l"(gptr));
}
#define CP_COMMIT() asm volatile("cp.async.commit_group;")
#define CP_WAIT0()  asm volatile("cp.async.wait_group 0;" ::: "memory")

// ================= weight conversion =================
// W [K x N] fp32 -> Bt hi/lo [N x K] row-major (transposed)
__global__ void convB_kernel(const float* __restrict__ W, __nv_bfloat16* __restrict__ hi,
                             __nv_bfloat16* __restrict__ lo, int K, int N) {
    int idx = blockIdx.x * blockDim.x + threadIdx.x;
    if (idx >= N * K) return;
    int n = idx / K, k = idx % K;
    float a = W[(size_t)k * N + n];
    __nv_bfloat16 h = __float2bfloat16(a);
    hi[idx] = h;
    lo[idx] = __float2bfloat16(a - __bfloat162float(h));
}

// ================= fused bf16x3 mma.sync GEMM (fp32 A in-kernel split) =================
// C[M x Ntot] = A[M x K] @ W where Bt = W^T [Ntot x K] bf16 hi/lo.
// Block 128x128, BK=64, 8 warps (2x4). Double-buffered smem; A reg-staged, B cp.async.
#define LDA 72
#define ASTG (128 * LDA * 2)          // 18432 B (one matrix, one stage)
#define STAGE (2 * ASTG)              // hi+lo = 36864 B
#define BREG 147456                   // B region base = 4 * ASTG... (2 stages A)
#define GEMM_SMEM (4 * STAGE)         // A 2 stages + B 2 stages = 147456
__global__ __launch_bounds__(256) void mma_gemm_kernel(
    const float* __restrict__ A,
    const __nv_bfloat16* __restrict__ Bh, const __nv_bfloat16* __restrict__ Bl,
    float* __restrict__ C, int Mreal, int Ntot, int K)
{
    extern __shared__ __align__(16) char smem[];
    uint32_t sbase = smem_to_u32(smem);

    int tid = threadIdx.x, wid = tid >> 5, lane = tid & 31;
    int mt = blockIdx.y, nt = blockIdx.x;
    int wm = wid >> 2;
    int wn = wid & 3;
    int nkc = K >> 6;

    float acc[4][4][4];
#pragma unroll
    for (int i = 0; i < 4; i++)
#pragma unroll
        for (int j = 0; j < 4; j++)
#pragma unroll
            for (int q = 0; q < 4; q++) acc[i][j][q] = 0.f;

    // A load mapping: 8 float4 per thread
    const int aIdxBase = tid;                 // +p*256
    // B load mapping: 4 cp.async(16B) per thread per matrix
    float4 aReg[8];

    // --- prologue: A chunk 0 into regs, B chunk 0 via cp.async ---
    {
        int k0 = 0;
#pragma unroll
        for (int p = 0; p < 8; p++) {
            int aIdx = p * 256 + aIdxBase;
            int arow = aIdx >> 4;
            int acol = (aIdx & 15) << 2;
            int gr = mt * 128 + arow;
            aReg[p] = (gr < Mreal) ? *(const float4*)(A + (size_t)gr * K + k0 + acol)
                                   : make_float4(0.f, 0.f, 0.f, 0.f);
        }
        uint32_t bB = sbase + 2 * STAGE;      // B stage 0
#pragma unroll
        for (int p = 0; p < 4; p++) {
            int bIdx = p * 256 + tid;
            int brow = bIdx >> 3;
            int bc = (bIdx & 7) * 8;
            const __nv_bfloat16* gh = Bh + (size_t)(nt * 128 + brow) * K + k0 + bc;
            const __nv_bfloat16* gl = Bl + (size_t)(nt * 128 + brow) * K + k0 + bc;
            uint32_t so = (uint32_t)(brow * LDA + bc) * 2;
            cpasync16(bB + so, gh);
            cpasync16(bB + ASTG + so, gl);
        }
        CP_COMMIT();
    }

    for (int kc = 0; kc < nkc; kc++) {
        int cur = kc & 1;
        uint32_t aS = sbase + cur * STAGE;
        uint32_t bS = sbase + 2 * STAGE + cur * STAGE;

        // STS A (split hi/lo) from regs
#pragma unroll
        for (int p = 0; p < 8; p++) {
            int aIdx = p * 256 + aIdxBase;
            int arow = aIdx >> 4;
            int acol = (aIdx & 15) << 2;
            float4 v = aReg[p];
            __nv_bfloat162 h01, h23, l01, l23;
            h01.x = __float2bfloat16(v.x); h01.y = __float2bfloat16(v.y);
            h23.x = __float2bfloat16(v.z); h23.y = __float2bfloat16(v.w);
            l01.x = __float2bfloat16(v.x - __bfloat162float(h01.x));
            l01.y = __float2bfloat16(v.y - __bfloat162float(h01.y));
            l23.x = __float2bfloat16(v.z - __bfloat162float(h23.x));
            l23.y = __float2bfloat16(v.w - __bfloat162float(h23.y));
            uint32_t so = (uint32_t)(arow * LDA + acol) * 2;
            *(__nv_bfloat162*)(smem + cur * STAGE + so)     = h01;
            *(__nv_bfloat162*)(smem + cur * STAGE + so + 4) = h23;
            *(__nv_bfloat162*)(smem + cur * STAGE + ASTG + so)     = l01;
            *(__nv_bfloat162*)(smem + cur * STAGE + ASTG + so + 4) = l23;
        }
        // prefetch next A chunk into regs (overlaps wait + compute)
        if (kc + 1 < nkc) {
            int k0 = (kc + 1) * 64;
#pragma unroll
            for (int p = 0; p < 8; p++) {
                int aIdx = p * 256 + aIdxBase;
                int arow = aIdx >> 4;
                int acol = (aIdx & 15) << 2;
                int gr = mt * 128 + arow;
                aReg[p] = (gr < Mreal) ? *(const float4*)(A + (size_t)gr * K + k0 + acol)
                                       : make_float4(0.f, 0.f, 0.f, 0.f);
            }
        }
        CP_WAIT0();           // B cur arrived
        __syncthreads();      // A STS visible; prior compute done

        // issue next B chunk
        if (kc + 1 < nkc) {
            int k0 = (kc + 1) * 64;
            uint32_t bN = sbase + 2 * STAGE + (cur ^ 1) * STAGE;
#pragma unroll
            for (int p = 0; p < 4; p++) {
                int bIdx = p * 256 + tid;
                int brow = bIdx >> 3;
                int bc = (bIdx & 7) * 8;
                const __nv_bfloat16* gh = Bh + (size_t)(nt * 128 + brow) * K + k0 + bc;
                const __nv_bfloat16* gl = Bl + (size_t)(nt * 128 + brow) * K + k0 + bc;
                uint32_t so = (uint32_t)(brow * LDA + bc) * 2;
                cpasync16(bN + so, gh);
                cpasync16(bN + ASTG + so, gl);
            }
            CP_COMMIT();
        }

        // compute chunk
#pragma unroll
        for (int ks = 0; ks < 4; ks++) {
            uint32_t ah[4][4], al[4][4], bh[4][2], bl[4][2];
            uint32_t arow = (uint32_t)(wm * 64 + (lane & 15));
            uint32_t acol = (uint32_t)(ks * 16 + (lane >> 4) * 8);
#pragma unroll
            for (int i = 0; i < 4; i++) {
                uint32_t off = ((arow + i * 16) * LDA + acol) * 2;
                ldsm_x4(ah[i], aS + off);
                ldsm_x4(al[i], aS + ASTG + off);
            }
            uint32_t brow = (uint32_t)(wn * 32 + (lane & 7));
            uint32_t bcol = (uint32_t)(ks * 16 + ((lane >> 3) & 1) * 8);
#pragma unroll
            for (int j = 0; j < 4; j++) {
                uint32_t off = ((brow + j * 8) * LDA + bcol) * 2;
                ldsm_x2(bh[j], bS + off);
                ldsm_x2(bl[j], bS + ASTG + off);
            }
#pragma unroll
            for (int i = 0; i < 4; i++)
#pragma unroll
                for (int j = 0; j < 4; j++) {
                    mma_bf16(acc[i][j], ah[i], bh[j]);
                    mma_bf16(acc[i][j], ah[i], bl[j]);
                    mma_bf16(acc[i][j], al[i], bh[j]);
                }
        }
        __syncthreads();
    }

    // epilogue
#pragma unroll
    for (int i = 0; i < 4; i++) {
        int r0 = mt * 128 + wm * 64 + i * 16 + (lane >> 2);
        int r1 = r0 + 8;
#pragma unroll
        for (int j = 0; j < 4; j++) {
            int c = nt * 128 + wn * 32 + j * 8 + (lane & 3) * 2;
            if (r0 < Mreal)
                *(float2*)(C + (size_t)r0 * Ntot + c) = make_float2(acc[i][j][0], acc[i][j][1]);
            if (r1 < Mreal)
                *(float2*)(C + (size_t)r1 * Ntot + c) = make_float2(acc[i][j][2], acc[i][j][3]);
        }
    }
}

// ================= CSR construction =================
__global__ void zero_int_kernel(int* p, int n) {
    int i = blockIdx.x * blockDim.x + threadIdx.x;
    if (i < n) p[i] = 0;
}

__global__ void hist_kernel(const int* __restrict__ ei, int* __restrict__ cnt) {
    int i = blockIdx.x * blockDim.x + threadIdx.x;
    if (i < NEDGE) atomicAdd(&cnt[ei[NEDGE + i]], 1);
}

__global__ __launch_bounds__(1024) void scan_kernel(const int* __restrict__ cnt,
                                                    int* __restrict__ indptr, int n) {
    __shared__ int part[1024];
    int tid = threadIdx.x;
    int chunk = (n + 1023) / 1024;
    int base = tid * chunk;
    int s = 0;
    for (int i = 0; i < chunk; i++)
        if (base + i < n) s += cnt[base + i];
    part[tid] = s;
    __syncthreads();
    for (int off = 1; off < 1024; off <<= 1) {
        int v = (tid >= off) ? part[tid - off] : 0;
        __syncthreads();
        part[tid] += v;
        __syncthreads();
    }
    int run = (tid == 0) ? 0 : part[tid - 1];
    for (int i = 0; i < chunk; i++) {
        if (base + i < n) {
            indptr[base + i] = run;
            run += cnt[base + i];
        }
    }
    if (tid == 1023) indptr[n] = part[1023];
}

__global__ void scatter_kernel(const int* __restrict__ ei, const float* __restrict__ ea,
                               const int* __restrict__ indptr, int* __restrict__ fill,
                               int* __restrict__ srccsr, float* __restrict__ eacsr) {
    int i = blockIdx.x * blockDim.x + threadIdx.x;
    if (i >= NEDGE) return;
    int dst = ei[NEDGE + i];
    int pos = indptr[dst] + atomicAdd(&fill[dst], 1);
    srccsr[pos] = ei[i];
    eacsr[pos] = ea[i];
}

// ================= fused GATv2 (online softmax, warp per (dst, head)) =================
template <int C>
__global__ void gat_fused_kernel(
    const float* __restrict__ xl, const float* __restrict__ xr, int ld,
    const int* __restrict__ indptr, const int* __restrict__ srccsr,
    const float* __restrict__ eacsr,
    const float* __restrict__ we, const float* __restrict__ att,
    float* __restrict__ out)
{
    const int H = 4, D = 4 * C, CH = C / 32;
    int wg = (blockIdx.x * blockDim.x + threadIdx.x) >> 5;
    int lane = threadIdx.x & 31;
    if (wg >= NNODE * H) return;
    int dst = wg >> 2, h = wg & 3;
    int p0 = indptr[dst], p1 = indptr[dst + 1];

    float xr_r[CH], we_r[CH], att_r[CH];
    const float* xrd = xr + (size_t)dst * ld + h * C;
#pragma unroll
    for (int j = 0; j < CH; j++) {
        int c = lane + j * 32;
        xr_r[j]  = xrd[c];
        we_r[j]  = we[h * C + c];
        att_r[j] = att[h * C + c];
    }

    float maxv = -INFINITY, denom = 0.f;
    float acc[CH];
#pragma unroll
    for (int j = 0; j < CH; j++) acc[j] = 0.f;

    for (int p = p0; p < p1; p++) {
        int src = srccsr[p];
        float eav = eacsr[p];
        const float* xls = xl + (size_t)src * ld + h * C;
        float xv[CH];
        float s = 0.f;
#pragma unroll
        for (int j = 0; j < CH; j++) {
            xv[j] = xls[lane + j * 32];
            float m = xv[j] + xr_r[j] + eav * we_r[j];
            m = m > 0.f ? m : NEG_SLOPE * m;
            s = fmaf(m, att_r[j], s);
        }
#pragma unroll
        for (int o = 16; o; o >>= 1) s += __shfl_xor_sync(0xffffffff, s, o);
        float mnew = fmaxf(maxv, s);
        float corr = expf(maxv - mnew);
        float w = expf(s - mnew);
        denom = denom * corr + w;
#pragma unroll
        for (int j = 0; j < CH; j++) acc[j] = fmaf(acc[j], corr, w * xv[j]);
        maxv = mnew;
    }

    float inv = 1.f / (denom + 1e-16f);
    float* od = out + (size_t)dst * D + h * C;
#pragma unroll
    for (int j = 0; j < CH; j++) od[lane + j * 32] = acc[j] * inv;
}

// ================= misc =================
__global__ void fill_kernel(float* p, float v, size_t n) {
    size_t i = (size_t)blockIdx.x * blockDim.x + threadIdx.x;
    size_t stride = (size_t)gridDim.x * blockDim.x;
    for (; i < n; i += stride) p[i] = v;
}

__global__ void bn_stats_kernel(
    const float* __restrict__ h, const float* __restrict__ bias,
    int n, int C, float* __restrict__ sums)
{
    int c = threadIdx.x;
    float b = bias ? bias[c] : 0.0f;
    int r0 = blockIdx.x * 64;
    int r1 = min(r0 + 64, n);
    float s = 0.0f, s2 = 0.0f;
    for (int r = r0; r < r1; r++) {
        float v = h[(size_t)r * C + c] + b;
        s += v;
        s2 += v * v;
    }
    atomicAdd(&sums[c], s);
    atomicAdd(&sums[C + c], s2);
}

__global__ void bn_apply_elu_kernel(
    float* __restrict__ h, const float* __restrict__ bias,
    const float* __restrict__ sums, const float* __restrict__ g,
    const float* __restrict__ b, int n, int C)
{
    size_t total = (size_t)n * C;
    size_t i = (size_t)blockIdx.x * blockDim.x + threadIdx.x;
    size_t stride = (size_t)gridDim.x * blockDim.x;
    float inv_n = 1.0f / n;
    for (; i < total; i += stride) {
        int c = (int)(i % C);
        float mu = sums[c] * inv_n;
        float var = sums[C + c] * inv_n - mu * mu;
        float v = h[i] + (bias ? bias[c] : 0.0f);
        v = (v - mu) * rsqrtf(var + BN_EPS) * g[c] + b[c];
        h[i] = v > 0.0f ? v : expm1f(v);
    }
}

__global__ void head_mean_kernel(const float* __restrict__ agg, float* __restrict__ h1)
{
    int idx = blockIdx.x * blockDim.x + threadIdx.x;
    if (idx >= NNODE * C1) return;
    int node = idx >> 6;
    int c = idx & 63;
    const float* a = agg + (size_t)node * D1;
    h1[idx] = 0.25f * (a[c] + a[64 + c] + a[128 + c] + a[192 + c]);
}

__global__ void pool_kernel(
    const float* __restrict__ h1, const int* __restrict__ batch,
    float* __restrict__ pool, float* __restrict__ cnt)
{
    int idx = blockIdx.x * blockDim.x + threadIdx.x;
    if (idx >= NNODE * 64) return;
    int node = idx >> 6;
    int c = idx & 63;
    int b = batch[node];
    atomicAdd(&pool[b * 64 + c], h1[idx]);
    if (c == 0) atomicAdd(&cnt[b], 1.0f);
}

__global__ __launch_bounds__(256) void classifier_kernel(
    const float* __restrict__ pool, const float* __restrict__ cnt,
    const float* __restrict__ w1, const float* __restrict__ b1,
    const float* __restrict__ bn1g, const float* __restrict__ bn1b,
    const float* __restrict__ w2, const float* __restrict__ b2,
    const float* __restrict__ bn2g, const float* __restrict__ bn2b,
    const float* __restrict__ w3, const float* __restrict__ b3,
    float* __restrict__ z1, float* __restrict__ z2,
    float* __restrict__ out, int out_size)
{
    __shared__ float emb[64 * 64];
    __shared__ float sc1[256], sh1[256];
    __shared__ float sc2[128], sh2[128];
    int tid = threadIdx.x;

    for (int i = tid; i < 64 * 64; i += 256) {
        int b = i >> 6;
        emb[i] = pool[i] / fmaxf(cnt[b], 1.0f);
    }
    __syncthreads();

    if (out_size >= 4224) {
        for (int i = tid; i < 4096; i += 256) out[128 + i] = emb[i];
    }

    for (int i = tid; i < 64 * 256; i += 256) {
        int b = i >> 8, j = i & 255;
        float s = b1[j];
        const float* er = emb + b * 64;
        for (int k = 0; k < 64; k++) s = fmaf(er[k], w1[k * 256 + j], s);
        z1[i] = s;
    }
    __syncthreads();

    if (tid < 256) {
        float s = 0.f, s2 = 0.f;
        for (int b = 0; b < 64; b++) {
            float v = z1[b * 256 + tid];
            s += v; s2 += v * v;
        }
        float mu = s / 64.f;
        float var = s2 / 64.f - mu * mu;
        float sc = rsqrtf(var + BN_EPS) * bn1g[tid];
        sc1[tid] = sc;
        sh1[tid] = bn1b[tid] - mu * sc;
    }
    __syncthreads();
    for (int i = tid; i < 64 * 256; i += 256) {
        float v = z1[i] * sc1[i & 255] + sh1[i & 255];
        z1[i] = v > 0.f ? v : expm1f(v);
    }
    __syncthreads();

    for (int i = tid; i < 64 * 128; i += 256) {
        int b = i >> 7, j = i & 127;
        float s = b2[j];
        const float* zr = z1 + b * 256;
        for (int k = 0; k < 256; k++) s = fmaf(zr[k], w2[k * 128 + j], s);
        z2[i] = s;
    }
    __syncthreads();

    if (tid < 128) {
        float s = 0.f, s2 = 0.f;
        for (int b = 0; b < 64; b++) {
            float v = z2[b * 128 + tid];
            s += v; s2 += v * v;
        }
        float mu = s / 64.f;
        float var = s2 / 64.f - mu * mu;
        float sc = rsqrtf(var + BN_EPS) * bn2g[tid];
        sc2[tid] = sc;
        sh2[tid] = bn2b[tid] - mu * sc;
    }
    __syncthreads();
    for (int i = tid; i < 64 * 128; i += 256) {
        float v = z2[i] * sc2[i & 127] + sh2[i & 127];
        z2[i] = v > 0.f ? v : expm1f(v);
    }
    __syncthreads();

    if (tid < 128) {
        int b = tid >> 1, j = tid & 1;
        float s = b3[j];
        const float* zr = z2 + b * 128;
        for (int k = 0; k < 128; k++) s = fmaf(zr[k], w3[k * 2 + j], s);
        if (out_size >= 128) out[b * 2 + j] = s;
    }
}

// ================= launch =================
extern "C" void kernel_launch(void* const* d_in, const int* in_sizes, int n_in,
                              void* d_out, int out_size)
{
    const float* x       = (const float*)d_in[0];
    const int*   ei      = (const int*)d_in[1];
    const float* ea      = (const float*)d_in[2];
    const int*   bat     = (const int*)d_in[3];
    const float* g0_wl   = (const float*)d_in[4];
    const float* g0_wr   = (const float*)d_in[5];
    const float* g0_we   = (const float*)d_in[6];
    const float* g0_att  = (const float*)d_in[7];
    const float* g0_bias = (const float*)d_in[8];
    const float* bn0_g   = (const float*)d_in[9];
    const float* bn0_b   = (const float*)d_in[10];
    const float* g1_wl   = (const float*)d_in[11];
    const float* g1_wr   = (const float*)d_in[12];
    const float* g1_we   = (const float*)d_in[13];
    const float* g1_att  = (const float*)d_in[14];
    const float* g1_bias = (const float*)d_in[15];
    const float* bn1_g   = (const float*)d_in[16];
    const float* bn1_b   = (const float*)d_in[17];
    const float* c_w1    = (const float*)d_in[18];
    const float* c_b1    = (const float*)d_in[19];
    const float* cbn1_g  = (const float*)d_in[20];
    const float* cbn1_b  = (const float*)d_in[21];
    const float* c_w2    = (const float*)d_in[22];
    const float* c_b2    = (const float*)d_in[23];
    const float* cbn2_g  = (const float*)d_in[24];
    const float* cbn2_b  = (const float*)d_in[25];
    const float* c_w3    = (const float*)d_in[26];
    const float* c_b3    = (const float*)d_in[27];
    float* out = (float*)d_out;

    float* S = nullptr;
    cudaGetSymbolAddress((void**)&S, g_scratch);
    __nv_bfloat16* BW = nullptr;
    cudaGetSymbolAddress((void**)&BW, g_bw);
    int* csr_cnt = nullptr;    cudaGetSymbolAddress((void**)&csr_cnt, g_cnt);
    int* indptr = nullptr;     cudaGetSymbolAddress((void**)&indptr, g_indptr);
    int* srccsr = nullptr;     cudaGetSymbolAddress((void**)&srccsr, g_srccsr);
    float* eacsr = nullptr;    cudaGetSymbolAddress((void**)&eacsr, g_eacsr);

    float* xlr0 = S + OFF_XLR0;
    float* h0   = S + OFF_H0;
    float* xlr1 = S + OFF_XLR1;
    float* agg1 = S + OFF_AGG1;
    float* h1   = S + OFF_H1;
    float* bns  = S + OFF_BNS;
    float* pool = S + OFF_POOL;
    float* cnt  = S + OFF_CNT;
    float* z1   = S + OFF_Z1;
    float* z2   = S + OFF_Z2;

    __nv_bfloat16* B0h = BW + BW_B0H;
    __nv_bfloat16* B0l = BW + BW_B0L;
    __nv_bfloat16* B1h = BW + BW_B1H;
    __nv_bfloat16* B1l = BW + BW_B1L;

    cudaFuncSetAttribute(mma_gemm_kernel, cudaFuncAttributeMaxDynamicSharedMemorySize, GEMM_SMEM);

    const int gatBlocks = (NNODE * 4 * 32 + 255) / 256;

    // ---- CSR build ----
    zero_int_kernel<<<(NNODE + 255) / 256, 256>>>(csr_cnt, NNODE);
    hist_kernel<<<(NEDGE + 255) / 256, 256>>>(ei, csr_cnt);
    scan_kernel<<<1, 1024>>>(csr_cnt, indptr, NNODE);
    zero_int_kernel<<<(NNODE + 255) / 256, 256>>>(csr_cnt, NNODE);
    scatter_kernel<<<(NEDGE + 255) / 256, 256>>>(ei, ea, indptr, csr_cnt, srccsr, eacsr);

    // ---- small fills ----
    fill_kernel<<<4, 256>>>(bns, 0.0f, 1024);
    fill_kernel<<<17, 256>>>(pool, 0.0f, 64 * 64 + 64);

    // ---- layer 0: weights + fused GEMM (xl|xr) ----
    convB_kernel<<<(D0 * INDIM + 255) / 256, 256>>>(g0_wl, B0h, B0l, INDIM, D0);
    convB_kernel<<<(D0 * INDIM + 255) / 256, 256>>>(g0_wr, B0h + (size_t)D0 * INDIM,
                                                    B0l + (size_t)D0 * INDIM, INDIM, D0);
    {
        dim3 gg(1024 / 128, NMT);
        mma_gemm_kernel<<<gg, 256, GEMM_SMEM>>>(x, B0h, B0l, xlr0, NNODE, 1024, INDIM);
    }

    gat_fused_kernel<C0><<<gatBlocks, 256>>>(xlr0, xlr0 + 512, 1024,
                                             indptr, srccsr, eacsr, g0_we, g0_att, h0);
    bn_stats_kernel<<<(NNODE + 63) / 64, D0>>>(h0, g0_bias, NNODE, D0, bns);
    bn_apply_elu_kernel<<<2048, 256>>>(h0, g0_bias, bns, bn0_g, bn0_b, NNODE, D0);

    // ---- layer 1 ----
    fill_kernel<<<4, 256>>>(bns, 0.0f, 1024);
    convB_kernel<<<(D1 * D0 + 255) / 256, 256>>>(g1_wl, B1h, B1l, D0, D1);
    convB_kernel<<<(D1 * D0 + 255) / 256, 256>>>(g1_wr, B1h + (size_t)D1 * D0,
                                                 B1l + (size_t)D1 * D0, D0, D1);
    {
        dim3 gg(512 / 128, NMT);
        mma_gemm_kernel<<<gg, 256, GEMM_SMEM>>>(h0, B1h, B1l, xlr1, NNODE, 512, D0);
    }

    gat_fused_kernel<C1><<<gatBlocks, 256>>>(xlr1, xlr1 + 256, 512,
                                             indptr, srccsr, eacsr, g1_we, g1_att, agg1);
    head_mean_kernel<<<(NNODE * C1 + 255) / 256, 256>>>(agg1, h1);
    bn_stats_kernel<<<(NNODE + 63) / 64, C1>>>(h1, g1_bias, NNODE, C1, bns);
    bn_apply_elu_kernel<<<1024, 256>>>(h1, g1_bias, bns, bn1_g, bn1_b, NNODE, C1);

    // ---- pool + classifier ----
    pool_kernel<<<(NNODE * 64 + 255) / 256, 256>>>(h1, bat, pool, cnt);
    classifier_kernel<<<1, 256>>>(pool, cnt,
                                  c_w1, c_b1, cbn1_g, cbn1_b,
                                  c_w2, c_b2, cbn2_g, cbn2_b,
                                  c_w3, c_b3, z1, z2, out, out_size);
}

// round 7
// speedup vs baseline: 2.3421x; 1.0777x over previous
#include <cuda_runtime.h>
#include <cuda_fp16.h>
#include <math.h>
#include <stdint.h>

// Problem constants
#define NNODE 20000
#define NEDGE 320000
#define INDIM 256
#define NB 64
#define H0 4
#define C0 128
#define D0 512   // H0*C0
#define H1 4
#define C1 64
#define D1 256   // H1*C1
#define NEG_SLOPE 0.2f
#define BN_EPS 1e-5f

#define MPAD 20096   // 157 * 128
#define NMT 157

// ---------------- fp32 scratch layout (floats) ----------------
#define OFF_XLR0 ((size_t)0)          // [NNODE x 1024]: xl0 cols 0-511, xr0 cols 512-1023
#define OFF_H0   ((size_t)20480000)   // [NNODE x 512]
#define OFF_XLR1 ((size_t)30720000)   // [NNODE x 512]: xl1 cols 0-255, xr1 cols 256-511
#define OFF_AGG1 ((size_t)40960000)   // [NNODE x 256]
#define OFF_H1   ((size_t)46080000)   // [NNODE x 64]
#define OFF_BNS  ((size_t)48800000)
#define OFF_POOL ((size_t)48801024)
#define OFF_CNT  ((size_t)48805120)
#define OFF_Z1   ((size_t)48805184)
#define OFF_Z2   ((size_t)48821568)
#define SCRATCH_FLOATS ((size_t)48829760)

__device__ __align__(256) float g_scratch[SCRATCH_FLOATS];

// ---------------- CSR scratch ----------------
__device__ int   g_cnt[NNODE];
__device__ int   g_indptr[NNODE + 1];
__device__ int   g_srccsr[NEDGE];
__device__ float g_eacsr[NEDGE];

// ---------------- fp16 weight scratch (transposed, hi/lo) ----------------
// B0: [1024 x 256] (wl rows 0-511, wr rows 512-1023), hi then lo
// B1: [512 x 512]  (wl rows 0-255, wr rows 256-511), hi then lo
#define BW_B0H ((size_t)0)
#define BW_B0L ((size_t)262144)
#define BW_B1H ((size_t)524288)
#define BW_B1L ((size_t)786432)
#define BW_TOTAL ((size_t)1048576)
__device__ __align__(1024) __half g_bw[BW_TOTAL];

// ================= PTX helpers (portable sm_80+ only) =================
__device__ __forceinline__ uint32_t smem_to_u32(const void* p) {
    uint32_t a;
    asm("{ .reg .u64 t; cvta.to.shared.u64 t, %1; cvt.u32.u64 %0, t; }" : "=r"(a) : "l"(p));
    return a;
}
__device__ __forceinline__ void ldsm_x4(uint32_t* r, uint32_t addr) {
    asm volatile("ldmatrix.sync.aligned.m8n8.x4.shared.b16 {%0,%1,%2,%3}, [%4];"
        : "=r"(r[0]), "=r"(r[1]), "=r"(r[2]), "=r"(r[3]) : "r"(addr));
}
__device__ __forceinline__ void ldsm_x2(uint32_t* r, uint32_t addr) {
    asm volatile("ldmatrix.sync.aligned.m8n8.x2.shared.b16 {%0,%1}, [%2];"
        : "=r"(r[0]), "=r"(r[1]) : "r"(addr));
}
__device__ __forceinline__ void mma_f16(float* d, const uint32_t* a, const uint32_t* b) {
    asm volatile(
        "mma.sync.aligned.m16n8k16.row.col.f32.f16.f16.f32 "
        "{%0,%1,%2,%3}, {%4,%5,%6,%7}, {%8,%9}, {%0,%1,%2,%3};"
        : "+f"(d[0]), "+f"(d[1]), "+f"(d[2]), "+f"(d[3])
        : "r"(a[0]), "r"(a[1]), "r"(a[2]), "r"(a[3]), "r"(b[0]), "r"(b[1]));
}
__device__ __forceinline__ void cpasync16(uint32_t saddr, const void* gptr) {
    asm volatile("cp.async.cg.shared.global [%0], [%1], 16;" :: "r"(saddr), "l"(gptr));
}
#define CP_COMMIT() asm volatile("cp.async.commit_group;")
#define CP_WAIT0()  asm volatile("cp.async.wait_group 0;" ::: "memory")

// ================= weight conversion =================
// W [K x N] fp32 -> Bt hi/lo fp16 [N x K] row-major (transposed)
__global__ void convB_kernel(const float* __restrict__ W, __half* __restrict__ hi,
                             __half* __restrict__ lo, int K, int N) {
    int idx = blockIdx.x * blockDim.x + threadIdx.x;
    if (idx >= N * K) return;
    int n = idx / K, k = idx % K;
    float a = W[(size_t)k * N + n];
    __half h = __float2half_rn(a);
    hi[idx] = h;
    lo[idx] = __float2half_rn(a - __half2float(h));
}

// ================= fp16 2-term mma.sync GEMM (fp32 A converted in-kernel) =================
// C[M x Ntot] = A[M x K] @ W where Bt = W^T [Ntot x K] fp16 hi/lo.
// Block 128x128, BK=64, 8 warps (2x4). Double-buffered; A reg-staged (single fp16), B cp.async.
#define LDA 72
#define ASTG (128 * LDA * 2)          // 18432 B (one matrix, one stage)
#define GEMM_SMEM (6 * ASTG)          // A: 2 stages x1 matrix, B: 2 stages x2 matrices
__global__ __launch_bounds__(256) void mma_gemm_kernel(
    const float* __restrict__ A,
    const __half* __restrict__ Bh, const __half* __restrict__ Bl,
    float* __restrict__ C, int Mreal, int Ntot, int K)
{
    extern __shared__ __align__(16) char smem[];
    uint32_t sbase = smem_to_u32(smem);

    int tid = threadIdx.x, wid = tid >> 5, lane = tid & 31;
    int mt = blockIdx.y, nt = blockIdx.x;
    int wm = wid >> 2;
    int wn = wid & 3;
    int nkc = K >> 6;

    float acc[4][4][4];
#pragma unroll
    for (int i = 0; i < 4; i++)
#pragma unroll
        for (int j = 0; j < 4; j++)
#pragma unroll
            for (int q = 0; q < 4; q++) acc[i][j][q] = 0.f;

    const int aIdxBase = tid;
    float4 aReg[8];

    // --- prologue: A chunk 0 into regs, B chunk 0 via cp.async ---
    {
        int k0 = 0;
#pragma unroll
        for (int p = 0; p < 8; p++) {
            int aIdx = p * 256 + aIdxBase;
            int arow = aIdx >> 4;
            int acol = (aIdx & 15) << 2;
            int gr = mt * 128 + arow;
            aReg[p] = (gr < Mreal) ? *(const float4*)(A + (size_t)gr * K + k0 + acol)
                                   : make_float4(0.f, 0.f, 0.f, 0.f);
        }
        uint32_t bB = sbase + 2 * ASTG;       // B stage 0 (hi at +0, lo at +ASTG)
#pragma unroll
        for (int p = 0; p < 4; p++) {
            int bIdx = p * 256 + tid;
            int brow = bIdx >> 3;
            int bc = (bIdx & 7) * 8;
            const __half* gh = Bh + (size_t)(nt * 128 + brow) * K + k0 + bc;
            const __half* gl = Bl + (size_t)(nt * 128 + brow) * K + k0 + bc;
            uint32_t so = (uint32_t)(brow * LDA + bc) * 2;
            cpasync16(bB + so, gh);
            cpasync16(bB + ASTG + so, gl);
        }
        CP_COMMIT();
    }

    for (int kc = 0; kc < nkc; kc++) {
        int cur = kc & 1;
        uint32_t aS = sbase + cur * ASTG;
        uint32_t bS = sbase + 2 * ASTG + cur * (2 * ASTG);

        // STS A (single fp16) from regs
#pragma unroll
        for (int p = 0; p < 8; p++) {
            int aIdx = p * 256 + aIdxBase;
            int arow = aIdx >> 4;
            int acol = (aIdx & 15) << 2;
            float4 v = aReg[p];
            __half2 h01, h23;
            h01.x = __float2half_rn(v.x); h01.y = __float2half_rn(v.y);
            h23.x = __float2half_rn(v.z); h23.y = __float2half_rn(v.w);
            uint32_t so = (uint32_t)(arow * LDA + acol) * 2;
            *(__half2*)(smem + cur * ASTG + so)     = h01;
            *(__half2*)(smem + cur * ASTG + so + 4) = h23;
        }
        // prefetch next A chunk into regs
        if (kc + 1 < nkc) {
            int k0 = (kc + 1) * 64;
#pragma unroll
            for (int p = 0; p < 8; p++) {
                int aIdx = p * 256 + aIdxBase;
                int arow = aIdx >> 4;
                int acol = (aIdx & 15) << 2;
                int gr = mt * 128 + arow;
                aReg[p] = (gr < Mreal) ? *(const float4*)(A + (size_t)gr * K + k0 + acol)
                                       : make_float4(0.f, 0.f, 0.f, 0.f);
            }
        }
        CP_WAIT0();
        __syncthreads();

        // issue next B chunk
        if (kc + 1 < nkc) {
            int k0 = (kc + 1) * 64;
            uint32_t bN = sbase + 2 * ASTG + (cur ^ 1) * (2 * ASTG);
#pragma unroll
            for (int p = 0; p < 4; p++) {
                int bIdx = p * 256 + tid;
                int brow = bIdx >> 3;
                int bc = (bIdx & 7) * 8;
                const __half* gh = Bh + (size_t)(nt * 128 + brow) * K + k0 + bc;
                const __half* gl = Bl + (size_t)(nt * 128 + brow) * K + k0 + bc;
                uint32_t so = (uint32_t)(brow * LDA + bc) * 2;
                cpasync16(bN + so, gh);
                cpasync16(bN + ASTG + so, gl);
            }
            CP_COMMIT();
        }

        // compute chunk: 2 MMAs per (i,j) — A16*Bh + A16*Bl
#pragma unroll
        for (int ks = 0; ks < 4; ks++) {
            uint32_t ah[4][4], bh[4][2], bl[4][2];
            uint32_t arow = (uint32_t)(wm * 64 + (lane & 15));
            uint32_t acol = (uint32_t)(ks * 16 + (lane >> 4) * 8);
#pragma unroll
            for (int i = 0; i < 4; i++) {
                uint32_t off = ((arow + i * 16) * LDA + acol) * 2;
                ldsm_x4(ah[i], aS + off);
            }
            uint32_t brow = (uint32_t)(wn * 32 + (lane & 7));
            uint32_t bcol = (uint32_t)(ks * 16 + ((lane >> 3) & 1) * 8);
#pragma unroll
            for (int j = 0; j < 4; j++) {
                uint32_t off = ((brow + j * 8) * LDA + bcol) * 2;
                ldsm_x2(bh[j], bS + off);
                ldsm_x2(bl[j], bS + ASTG + off);
            }
#pragma unroll
            for (int i = 0; i < 4; i++)
#pragma unroll
                for (int j = 0; j < 4; j++) {
                    mma_f16(acc[i][j], ah[i], bh[j]);
                    mma_f16(acc[i][j], ah[i], bl[j]);
                }
        }
        __syncthreads();
    }

    // epilogue
#pragma unroll
    for (int i = 0; i < 4; i++) {
        int r0 = mt * 128 + wm * 64 + i * 16 + (lane >> 2);
        int r1 = r0 + 8;
#pragma unroll
        for (int j = 0; j < 4; j++) {
            int c = nt * 128 + wn * 32 + j * 8 + (lane & 3) * 2;
            if (r0 < Mreal)
                *(float2*)(C + (size_t)r0 * Ntot + c) = make_float2(acc[i][j][0], acc[i][j][1]);
            if (r1 < Mreal)
                *(float2*)(C + (size_t)r1 * Ntot + c) = make_float2(acc[i][j][2], acc[i][j][3]);
        }
    }
}

// ================= CSR construction =================
__global__ void zero_int_kernel(int* p, int n) {
    int i = blockIdx.x * blockDim.x + threadIdx.x;
    if (i < n) p[i] = 0;
}

__global__ void hist_kernel(const int* __restrict__ ei, int* __restrict__ cnt) {
    int i = blockIdx.x * blockDim.x + threadIdx.x;
    if (i < NEDGE) atomicAdd(&cnt[ei[NEDGE + i]], 1);
}

__global__ __launch_bounds__(1024) void scan_kernel(const int* __restrict__ cnt,
                                                    int* __restrict__ indptr, int n) {
    __shared__ int part[1024];
    int tid = threadIdx.x;
    int chunk = (n + 1023) / 1024;
    int base = tid * chunk;
    int s = 0;
    for (int i = 0; i < chunk; i++)
        if (base + i < n) s += cnt[base + i];
    part[tid] = s;
    __syncthreads();
    for (int off = 1; off < 1024; off <<= 1) {
        int v = (tid >= off) ? part[tid - off] : 0;
        __syncthreads();
        part[tid] += v;
        __syncthreads();
    }
    int run = (tid == 0) ? 0 : part[tid - 1];
    for (int i = 0; i < chunk; i++) {
        if (base + i < n) {
            indptr[base + i] = run;
            run += cnt[base + i];
        }
    }
    if (tid == 1023) indptr[n] = part[1023];
}

__global__ void scatter_kernel(const int* __restrict__ ei, const float* __restrict__ ea,
                               const int* __restrict__ indptr, int* __restrict__ fill,
                               int* __restrict__ srccsr, float* __restrict__ eacsr) {
    int i = blockIdx.x * blockDim.x + threadIdx.x;
    if (i >= NEDGE) return;
    int dst = ei[NEDGE + i];
    int pos = indptr[dst] + atomicAdd(&fill[dst], 1);
    srccsr[pos] = ei[i];
    eacsr[pos] = ea[i];
}

// ================= fused GATv2 (online softmax, warp per (dst, head)) =================
template <int C>
__global__ void gat_fused_kernel(
    const float* __restrict__ xl, const float* __restrict__ xr, int ld,
    const int* __restrict__ indptr, const int* __restrict__ srccsr,
    const float* __restrict__ eacsr,
    const float* __restrict__ we, const float* __restrict__ att,
    float* __restrict__ out)
{
    const int H = 4, D = 4 * C, CH = C / 32;
    int wg = (blockIdx.x * blockDim.x + threadIdx.x) >> 5;
    int lane = threadIdx.x & 31;
    if (wg >= NNODE * H) return;
    int dst = wg >> 2, h = wg & 3;
    int p0 = indptr[dst], p1 = indptr[dst + 1];

    float xr_r[CH], we_r[CH], att_r[CH];
    const float* xrd = xr + (size_t)dst * ld + h * C;
#pragma unroll
    for (int j = 0; j < CH; j++) {
        int c = lane + j * 32;
        xr_r[j]  = xrd[c];
        we_r[j]  = we[h * C + c];
        att_r[j] = att[h * C + c];
    }

    float maxv = -INFINITY, denom = 0.f;
    float acc[CH];
#pragma unroll
    for (int j = 0; j < CH; j++) acc[j] = 0.f;

    for (int p = p0; p < p1; p++) {
        int src = srccsr[p];
        float eav = eacsr[p];
        const float* xls = xl + (size_t)src * ld + h * C;
        float xv[CH];
        float s = 0.f;
#pragma unroll
        for (int j = 0; j < CH; j++) {
            xv[j] = xls[lane + j * 32];
            float m = xv[j] + xr_r[j] + eav * we_r[j];
            m = m > 0.f ? m : NEG_SLOPE * m;
            s = fmaf(m, att_r[j], s);
        }
#pragma unroll
        for (int o = 16; o; o >>= 1) s += __shfl_xor_sync(0xffffffff, s, o);
        float mnew = fmaxf(maxv, s);
        float corr = expf(maxv - mnew);
        float w = expf(s - mnew);
        denom = denom * corr + w;
#pragma unroll
        for (int j = 0; j < CH; j++) acc[j] = fmaf(acc[j], corr, w * xv[j]);
        maxv = mnew;
    }

    float inv = 1.f / (denom + 1e-16f);
    float* od = out + (size_t)dst * D + h * C;
#pragma unroll
    for (int j = 0; j < CH; j++) od[lane + j * 32] = acc[j] * inv;
}

// ================= misc =================
__global__ void fill_kernel(float* p, float v, size_t n) {
    size_t i = (size_t)blockIdx.x * blockDim.x + threadIdx.x;
    size_t stride = (size_t)gridDim.x * blockDim.x;
    for (; i < n; i += stride) p[i] = v;
}

__global__ void bn_stats_kernel(
    const float* __restrict__ h, const float* __restrict__ bias,
    int n, int C, float* __restrict__ sums)
{
    int c = threadIdx.x;
    float b = bias ? bias[c] : 0.0f;
    int r0 = blockIdx.x * 64;
    int r1 = min(r0 + 64, n);
    float s = 0.0f, s2 = 0.0f;
    for (int r = r0; r < r1; r++) {
        float v = h[(size_t)r * C + c] + b;
        s += v;
        s2 += v * v;
    }
    atomicAdd(&sums[c], s);
    atomicAdd(&sums[C + c], s2);
}

__global__ void bn_apply_elu_kernel(
    float* __restrict__ h, const float* __restrict__ bias,
    const float* __restrict__ sums, const float* __restrict__ g,
    const float* __restrict__ b, int n, int C)
{
    size_t total = (size_t)n * C;
    size_t i = (size_t)blockIdx.x * blockDim.x + threadIdx.x;
    size_t stride = (size_t)gridDim.x * blockDim.x;
    float inv_n = 1.0f / n;
    for (; i < total; i += stride) {
        int c = (int)(i % C);
        float mu = sums[c] * inv_n;
        float var = sums[C + c] * inv_n - mu * mu;
        float v = h[i] + (bias ? bias[c] : 0.0f);
        v = (v - mu) * rsqrtf(var + BN_EPS) * g[c] + b[c];
        h[i] = v > 0.0f ? v : expm1f(v);
    }
}

__global__ void head_mean_kernel(const float* __restrict__ agg, float* __restrict__ h1)
{
    int idx = blockIdx.x * blockDim.x + threadIdx.x;
    if (idx >= NNODE * C1) return;
    int node = idx >> 6;
    int c = idx & 63;
    const float* a = agg + (size_t)node * D1;
    h1[idx] = 0.25f * (a[c] + a[64 + c] + a[128 + c] + a[192 + c]);
}

__global__ void pool_kernel(
    const float* __restrict__ h1, const int* __restrict__ batch,
    float* __restrict__ pool, float* __restrict__ cnt)
{
    int idx = blockIdx.x * blockDim.x + threadIdx.x;
    if (idx >= NNODE * 64) return;
    int node = idx >> 6;
    int c = idx & 63;
    int b = batch[node];
    atomicAdd(&pool[b * 64 + c], h1[idx]);
    if (c == 0) atomicAdd(&cnt[b], 1.0f);
}

__global__ __launch_bounds__(256) void classifier_kernel(
    const float* __restrict__ pool, const float* __restrict__ cnt,
    const float* __restrict__ w1, const float* __restrict__ b1,
    const float* __restrict__ bn1g, const float* __restrict__ bn1b,
    const float* __restrict__ w2, const float* __restrict__ b2,
    const float* __restrict__ bn2g, const float* __restrict__ bn2b,
    const float* __restrict__ w3, const float* __restrict__ b3,
    float* __restrict__ z1, float* __restrict__ z2,
    float* __restrict__ out, int out_size)
{
    __shared__ float emb[64 * 64];
    __shared__ float sc1[256], sh1[256];
    __shared__ float sc2[128], sh2[128];
    int tid = threadIdx.x;

    for (int i = tid; i < 64 * 64; i += 256) {
        int b = i >> 6;
        emb[i] = pool[i] / fmaxf(cnt[b], 1.0f);
    }
    __syncthreads();

    if (out_size >= 4224) {
        for (int i = tid; i < 4096; i += 256) out[128 + i] = emb[i];
    }

    for (int i = tid; i < 64 * 256; i += 256) {
        int b = i >> 8, j = i & 255;
        float s = b1[j];
        const float* er = emb + b * 64;
        for (int k = 0; k < 64; k++) s = fmaf(er[k], w1[k * 256 + j], s);
        z1[i] = s;
    }
    __syncthreads();

    if (tid < 256) {
        float s = 0.f, s2 = 0.f;
        for (int b = 0; b < 64; b++) {
            float v = z1[b * 256 + tid];
            s += v; s2 += v * v;
        }
        float mu = s / 64.f;
        float var = s2 / 64.f - mu * mu;
        float sc = rsqrtf(var + BN_EPS) * bn1g[tid];
        sc1[tid] = sc;
        sh1[tid] = bn1b[tid] - mu * sc;
    }
    __syncthreads();
    for (int i = tid; i < 64 * 256; i += 256) {
        float v = z1[i] * sc1[i & 255] + sh1[i & 255];
        z1[i] = v > 0.f ? v : expm1f(v);
    }
    __syncthreads();

    for (int i = tid; i < 64 * 128; i += 256) {
        int b = i >> 7, j = i & 127;
        float s = b2[j];
        const float* zr = z1 + b * 256;
        for (int k = 0; k < 256; k++) s = fmaf(zr[k], w2[k * 128 + j], s);
        z2[i] = s;
    }
    __syncthreads();

    if (tid < 128) {
        float s = 0.f, s2 = 0.f;
        for (int b = 0; b < 64; b++) {
            float v = z2[b * 128 + tid];
            s += v; s2 += v * v;
        }
        float mu = s / 64.f;
        float var = s2 / 64.f - mu * mu;
        float sc = rsqrtf(var + BN_EPS) * bn2g[tid];
        sc2[tid] = sc;
        sh2[tid] = bn2b[tid] - mu * sc;
    }
    __syncthreads();
    for (int i = tid; i < 64 * 128; i += 256) {
        float v = z2[i] * sc2[i & 127] + sh2[i & 127];
        z2[i] = v > 0.f ? v : expm1f(v);
    }
    __syncthreads();

    if (tid < 128) {
        int b = tid >> 1, j = tid & 1;
        float s = b3[j];
        const float* zr = z2 + b * 128;
        for (int k = 0; k < 128; k++) s = fmaf(zr[k], w3[k * 2 + j], s);
        if (out_size >= 128) out[b * 2 + j] = s;
    }
}

// ================= launch =================
extern "C" void kernel_launch(void* const* d_in, const int* in_sizes, int n_in,
                              void* d_out, int out_size)
{
    const float* x       = (const float*)d_in[0];
    const int*   ei      = (const int*)d_in[1];
    const float* ea      = (const float*)d_in[2];
    const int*   bat     = (const int*)d_in[3];
    const float* g0_wl   = (const float*)d_in[4];
    const float* g0_wr   = (const float*)d_in[5];
    const float* g0_we   = (const float*)d_in[6];
    const float* g0_att  = (const float*)d_in[7];
    const float* g0_bias = (const float*)d_in[8];
    const float* bn0_g   = (const float*)d_in[9];
    const float* bn0_b   = (const float*)d_in[10];
    const float* g1_wl   = (const float*)d_in[11];
    const float* g1_wr   = (const float*)d_in[12];
    const float* g1_we   = (const float*)d_in[13];
    const float* g1_att  = (const float*)d_in[14];
    const float* g1_bias = (const float*)d_in[15];
    const float* bn1_g   = (const float*)d_in[16];
    const float* bn1_b   = (const float*)d_in[17];
    const float* c_w1    = (const float*)d_in[18];
    const float* c_b1    = (const float*)d_in[19];
    const float* cbn1_g  = (const float*)d_in[20];
    const float* cbn1_b  = (const float*)d_in[21];
    const float* c_w2    = (const float*)d_in[22];
    const float* c_b2    = (const float*)d_in[23];
    const float* cbn2_g  = (const float*)d_in[24];
    const float* cbn2_b  = (const float*)d_in[25];
    const float* c_w3    = (const float*)d_in[26];
    const float* c_b3    = (const float*)d_in[27];
    float* out = (float*)d_out;

    float* S = nullptr;
    cudaGetSymbolAddress((void**)&S, g_scratch);
    __half* BW = nullptr;
    cudaGetSymbolAddress((void**)&BW, g_bw);
    int* csr_cnt = nullptr;    cudaGetSymbolAddress((void**)&csr_cnt, g_cnt);
    int* indptr = nullptr;     cudaGetSymbolAddress((void**)&indptr, g_indptr);
    int* srccsr = nullptr;     cudaGetSymbolAddress((void**)&srccsr, g_srccsr);
    float* eacsr = nullptr;    cudaGetSymbolAddress((void**)&eacsr, g_eacsr);

    float* xlr0 = S + OFF_XLR0;
    float* h0   = S + OFF_H0;
    float* xlr1 = S + OFF_XLR1;
    float* agg1 = S + OFF_AGG1;
    float* h1   = S + OFF_H1;
    float* bns  = S + OFF_BNS;
    float* pool = S + OFF_POOL;
    float* cnt  = S + OFF_CNT;
    float* z1   = S + OFF_Z1;
    float* z2   = S + OFF_Z2;

    __half* B0h = BW + BW_B0H;
    __half* B0l = BW + BW_B0L;
    __half* B1h = BW + BW_B1H;
    __half* B1l = BW + BW_B1L;

    cudaFuncSetAttribute(mma_gemm_kernel, cudaFuncAttributeMaxDynamicSharedMemorySize, GEMM_SMEM);

    const int gatBlocks = (NNODE * 4 * 32 + 255) / 256;

    // ---- CSR build ----
    zero_int_kernel<<<(NNODE + 255) / 256, 256>>>(csr_cnt, NNODE);
    hist_kernel<<<(NEDGE + 255) / 256, 256>>>(ei, csr_cnt);
    scan_kernel<<<1, 1024>>>(csr_cnt, indptr, NNODE);
    zero_int_kernel<<<(NNODE + 255) / 256, 256>>>(csr_cnt, NNODE);
    scatter_kernel<<<(NEDGE + 255) / 256, 256>>>(ei, ea, indptr, csr_cnt, srccsr, eacsr);

    // ---- small fills ----
    fill_kernel<<<4, 256>>>(bns, 0.0f, 1024);
    fill_kernel<<<17, 256>>>(pool, 0.0f, 64 * 64 + 64);

    // ---- layer 0: weights + fused GEMM (xl|xr) ----
    convB_kernel<<<(D0 * INDIM + 255) / 256, 256>>>(g0_wl, B0h, B0l, INDIM, D0);
    convB_kernel<<<(D0 * INDIM + 255) / 256, 256>>>(g0_wr, B0h + (size_t)D0 * INDIM,
                                                    B0l + (size_t)D0 * INDIM, INDIM, D0);
    {
        dim3 gg(1024 / 128, NMT);
        mma_gemm_kernel<<<gg, 256, GEMM_SMEM>>>(x, B0h, B0l, xlr0, NNODE, 1024, INDIM);
    }

    gat_fused_kernel<C0><<<gatBlocks, 256>>>(xlr0, xlr0 + 512, 1024,
                                             indptr, srccsr, eacsr, g0_we, g0_att, h0);
    bn_stats_kernel<<<(NNODE + 63) / 64, D0>>>(h0, g0_bias, NNODE, D0, bns);
    bn_apply_elu_kernel<<<2048, 256>>>(h0, g0_bias, bns, bn0_g, bn0_b, NNODE, D0);

    // ---- layer 1 ----
    fill_kernel<<<4, 256>>>(bns, 0.0f, 1024);
    convB_kernel<<<(D1 * D0 + 255) / 256, 256>>>(g1_wl, B1h, B1l, D0, D1);
    convB_kernel<<<(D1 * D0 + 255) / 256, 256>>>(g1_wr, B1h + (size_t)D1 * D0,
                                                 B1l + (size_t)D1 * D0, D0, D1);
    {
        dim3 gg(512 / 128, NMT);
        mma_gemm_kernel<<<gg, 256, GEMM_SMEM>>>(h0, B1h, B1l, xlr1, NNODE, 512, D0);
    }

    gat_fused_kernel<C1><<<gatBlocks, 256>>>(xlr1, xlr1 + 256, 512,
                                             indptr, srccsr, eacsr, g1_we, g1_att, agg1);
    head_mean_kernel<<<(NNODE * C1 + 255) / 256, 256>>>(agg1, h1);
    bn_stats_kernel<<<(NNODE + 63) / 64, C1>>>(h1, g1_bias, NNODE, C1, bns);
    bn_apply_elu_kernel<<<1024, 256>>>(h1, g1_bias, bns, bn1_g, bn1_b, NNODE, C1);

    // ---- pool + classifier ----
    pool_kernel<<<(NNODE * 64 + 255) / 256, 256>>>(h1, bat, pool, cnt);
    classifier_kernel<<<1, 256>>>(pool, cnt,
                                  c_w1, c_b1, cbn1_g, cbn1_b,
                                  c_w2, c_b2, cbn2_g, cbn2_b,
                                  c_w3, c_b3, z1, z2, out, out_size);
}